// round 1
// baseline (speedup 1.0000x reference)
#include <cuda_runtime.h>
#include <cuda_bf16.h>
#include <cstdint>

// Problem constants
#define Bb   2
#define Ss   2048
#define HID  1024
#define NH   16
#define NKV  8
#define HD   128
#define MROWS (Bb*Ss)          // 4096
#define QDIM (NH*HD)           // 2048
#define KDIM (NKV*HD)          // 1024
#define SCALE 0.08838834764831845f

// Scratch (static device memory; no allocation APIs)
__device__ float g_qbuf[(size_t)MROWS * QDIM];
__device__ float g_kbuf[(size_t)MROWS * KDIM];
__device__ float g_vbuf[(size_t)MROWS * KDIM];
__device__ float g_qT[(size_t)Bb * NH * Ss * HD];
__device__ float g_kT[(size_t)Bb * NKV * Ss * HD];
__device__ float g_vT[(size_t)Bb * NKV * Ss * HD];
__device__ float g_attn[(size_t)MROWS * QDIM];

// ---------------------------------------------------------------------------
// SGEMM: C[M][N] = A[M][K] * B[N][K]^T  (both operands K-contiguous, row-major)
// BM=BN=128, BK=8, 256 threads, 8x8 microtile.
// ---------------------------------------------------------------------------
__global__ __launch_bounds__(256) void sgemm_abt(const float* __restrict__ A,
                                                 const float* __restrict__ B,
                                                 float* __restrict__ C,
                                                 int M, int N, int K) {
    __shared__ float As[8][132];
    __shared__ float Bs[8][132];
    int tid = threadIdx.x;
    int r0 = blockIdx.y * 128;
    int c0 = blockIdx.x * 128;
    int tx = tid & 15, ty = tid >> 4;
    int lr = tid >> 1;           // 0..127
    int lk = (tid & 1) * 4;      // 0 or 4

    const float* Ar = A + (size_t)(r0 + lr) * K + lk;
    const float* Br = B + (size_t)(c0 + lr) * K + lk;

    float acc[8][8];
#pragma unroll
    for (int i = 0; i < 8; i++)
#pragma unroll
        for (int j = 0; j < 8; j++) acc[i][j] = 0.f;

    for (int k0 = 0; k0 < K; k0 += 8) {
        float4 a  = *(const float4*)(Ar + k0);
        float4 bb = *(const float4*)(Br + k0);
        As[lk + 0][lr] = a.x;  As[lk + 1][lr] = a.y;
        As[lk + 2][lr] = a.z;  As[lk + 3][lr] = a.w;
        Bs[lk + 0][lr] = bb.x; Bs[lk + 1][lr] = bb.y;
        Bs[lk + 2][lr] = bb.z; Bs[lk + 3][lr] = bb.w;
        __syncthreads();
#pragma unroll
        for (int k = 0; k < 8; k++) {
            float ra[8], rb[8];
            *(float4*)(ra)     = *(const float4*)&As[k][ty * 8];
            *(float4*)(ra + 4) = *(const float4*)&As[k][ty * 8 + 4];
            *(float4*)(rb)     = *(const float4*)&Bs[k][tx * 8];
            *(float4*)(rb + 4) = *(const float4*)&Bs[k][tx * 8 + 4];
#pragma unroll
            for (int i = 0; i < 8; i++)
#pragma unroll
                for (int j = 0; j < 8; j++)
                    acc[i][j] += ra[i] * rb[j];
        }
        __syncthreads();
    }

#pragma unroll
    for (int i = 0; i < 8; i++) {
        float* cp = C + (size_t)(r0 + ty * 8 + i) * N + c0 + tx * 8;
        float4 v0 = make_float4(acc[i][0], acc[i][1], acc[i][2], acc[i][3]);
        float4 v1 = make_float4(acc[i][4], acc[i][5], acc[i][6], acc[i][7]);
        *(float4*)(cp)     = v0;
        *(float4*)(cp + 4) = v1;
    }
}

// ---------------------------------------------------------------------------
// RMSNorm + RoPE + transpose. One warp handles one (b,s,head-vector).
// Lane l owns dims {l, l+32, l+64, l+96} so rotate-half pairs are intra-lane.
// hh in [0,16): Q head; [16,24): K head; [24,32): V head (copy only).
// ---------------------------------------------------------------------------
__global__ __launch_bounds__(256) void normrope_kernel(const float* __restrict__ cosb,
                                                       const float* __restrict__ sinb,
                                                       const float* __restrict__ qw,
                                                       const float* __restrict__ kw) {
    int gwarp = (blockIdx.x * blockDim.x + threadIdx.x) >> 5;
    int lane = threadIdx.x & 31;
    int row = gwarp >> 5;       // b*S + s
    int hh  = gwarp & 31;
    int b = row >> 11;          // /2048
    int s = row & 2047;

    const float* src;
    float* dst;
    const float* w = qw;
    bool dorm = true;
    if (hh < 16) {
        src = g_qbuf + (size_t)row * QDIM + hh * HD;
        dst = g_qT + (((size_t)b * NH + hh) * Ss + s) * HD;
        w = qw;
    } else if (hh < 24) {
        int h = hh - 16;
        src = g_kbuf + (size_t)row * KDIM + h * HD;
        dst = g_kT + (((size_t)b * NKV + h) * Ss + s) * HD;
        w = kw;
    } else {
        int h = hh - 24;
        src = g_vbuf + (size_t)row * KDIM + h * HD;
        dst = g_vT + (((size_t)b * NKV + h) * Ss + s) * HD;
        dorm = false;
    }

    float x0 = src[lane], x1 = src[lane + 32], x2 = src[lane + 64], x3 = src[lane + 96];

    if (dorm) {
        float ss = x0 * x0 + x1 * x1 + x2 * x2 + x3 * x3;
#pragma unroll
        for (int o = 16; o; o >>= 1) ss += __shfl_xor_sync(0xffffffffu, ss, o);
        float inv = rsqrtf(ss * (1.0f / 128.0f) + 1e-6f);
        x0 = x0 * inv * w[lane];
        x1 = x1 * inv * w[lane + 32];
        x2 = x2 * inv * w[lane + 64];
        x3 = x3 * inv * w[lane + 96];
        // RoPE
        const float* cp = cosb + (size_t)row * HD;
        const float* sp = sinb + (size_t)row * HD;
        float c0 = cp[lane], c1 = cp[lane + 32], c2 = cp[lane + 64], c3 = cp[lane + 96];
        float s0 = sp[lane], s1 = sp[lane + 32], s2 = sp[lane + 64], s3 = sp[lane + 96];
        float y0 = x0 * c0 - x2 * s0;
        float y1 = x1 * c1 - x3 * s1;
        float y2 = x2 * c2 + x0 * s2;
        float y3 = x3 * c3 + x1 * s3;
        x0 = y0; x1 = y1; x2 = y2; x3 = y3;
    }

    dst[lane] = x0; dst[lane + 32] = x1; dst[lane + 64] = x2; dst[lane + 96] = x3;
}

// ---------------------------------------------------------------------------
// fp32 flash attention, causal, GQA (kv head = h>>1).
// Block: 256 threads, BM=64 queries (4 threads per query), BN=32 key tile.
// Thread sub in [0,4) owns dim chunks d = sub*4 + 16*i (i=0..7) -> conflict-free
// LDS.128 on K/V tiles. Output written transposed into g_attn[b*S+q][h*HD+d].
// ---------------------------------------------------------------------------
__global__ __launch_bounds__(256) void flash_kernel() {
    int tid = threadIdx.x;
    int m   = tid >> 2;       // 0..63 (query within tile)
    int sub = tid & 3;        // dim group
    int q0 = blockIdx.x * 64;
    int h  = blockIdx.y;
    int b  = blockIdx.z;
    int hk = h >> 1;
    int qglob = q0 + m;

    __shared__ float Ks[32 * 128];
    __shared__ float Vs[32 * 128];

    const float* qptr = g_qT + (((size_t)b * NH + h) * Ss + qglob) * HD;
    float qreg[32], o[32];
#pragma unroll
    for (int i = 0; i < 8; i++) {
        float4 t = *(const float4*)(qptr + sub * 4 + 16 * i);
        qreg[4 * i + 0] = t.x; qreg[4 * i + 1] = t.y;
        qreg[4 * i + 2] = t.z; qreg[4 * i + 3] = t.w;
    }
#pragma unroll
    for (int i = 0; i < 32; i++) o[i] = 0.f;

    float mrow = -1e30f, lrow = 0.f;

    const float* kb = g_kT + (((size_t)b * NKV + hk) * Ss) * HD;
    const float* vb = g_vT + (((size_t)b * NKV + hk) * Ss) * HD;

    int ntiles = (q0 + 64) >> 5;
    for (int t = 0; t < ntiles; t++) {
        int n0 = t * 32;
        const float4* ksrc = (const float4*)(kb + (size_t)n0 * HD);
        const float4* vsrc = (const float4*)(vb + (size_t)n0 * HD);
        float4* kd = (float4*)Ks;
        float4* vd = (float4*)Vs;
#pragma unroll
        for (int r = 0; r < 4; r++) {
            int lin = tid + r * 256;
            kd[lin] = ksrc[lin];
            vd[lin] = vsrc[lin];
        }
        __syncthreads();

        float sv[32];
        const float4* K4 = (const float4*)Ks;
#pragma unroll
        for (int n = 0; n < 32; n++) {
            const float4* kp = K4 + n * 32 + sub;
            float d0 = 0.f, d1 = 0.f, d2 = 0.f, d3 = 0.f;
#pragma unroll
            for (int i = 0; i < 8; i++) {
                float4 kv = kp[4 * i];
                d0 += qreg[4 * i + 0] * kv.x;
                d1 += qreg[4 * i + 1] * kv.y;
                d2 += qreg[4 * i + 2] * kv.z;
                d3 += qreg[4 * i + 3] * kv.w;
            }
            float dot = (d0 + d1) + (d2 + d3);
            dot += __shfl_xor_sync(0xffffffffu, dot, 1);
            dot += __shfl_xor_sync(0xffffffffu, dot, 2);
            float sc = dot * SCALE;
            if (n0 + n > qglob) sc = -1e9f;     // causal mask (matches ref NEG)
            sv[n] = sc;
        }

        float tmax = sv[0];
#pragma unroll
        for (int n = 1; n < 32; n++) tmax = fmaxf(tmax, sv[n]);
        float mnew = fmaxf(mrow, tmax);
        float corr = __expf(mrow - mnew);
        lrow *= corr;
#pragma unroll
        for (int i = 0; i < 32; i++) o[i] *= corr;

        const float4* V4 = (const float4*)Vs;
#pragma unroll
        for (int n = 0; n < 32; n++) {
            float p = __expf(sv[n] - mnew);
            lrow += p;
            const float4* vp = V4 + n * 32 + sub;
#pragma unroll
            for (int i = 0; i < 8; i++) {
                float4 vv = vp[4 * i];
                o[4 * i + 0] += p * vv.x;
                o[4 * i + 1] += p * vv.y;
                o[4 * i + 2] += p * vv.z;
                o[4 * i + 3] += p * vv.w;
            }
        }
        mrow = mnew;
        __syncthreads();
    }

    float inv = 1.0f / lrow;
    float* ob = g_attn + ((size_t)(b * Ss + qglob) * NH + h) * HD;
#pragma unroll
    for (int i = 0; i < 8; i++) {
        float4 v = make_float4(o[4 * i + 0] * inv, o[4 * i + 1] * inv,
                               o[4 * i + 2] * inv, o[4 * i + 3] * inv);
        *(float4*)(ob + sub * 4 + 16 * i) = v;
    }
}

// ---------------------------------------------------------------------------
extern "C" void kernel_launch(void* const* d_in, const int* in_sizes, int n_in,
                              void* d_out, int out_size) {
    const float* x    = (const float*)d_in[0];
    const float* cosb = (const float*)d_in[1];
    const float* sinb = (const float*)d_in[2];
    // d_in[3] = attention_mask (causal, recomputed implicitly)
    const float* Wq = (const float*)d_in[4];
    const float* Wk = (const float*)d_in[5];
    const float* Wv = (const float*)d_in[6];
    const float* Wo = (const float*)d_in[7];
    const float* qw = (const float*)d_in[8];
    const float* kw = (const float*)d_in[9];
    float* out = (float*)d_out;

    float *qbuf, *kbuf, *vbuf, *attn;
    cudaGetSymbolAddress((void**)&qbuf, g_qbuf);
    cudaGetSymbolAddress((void**)&kbuf, g_kbuf);
    cudaGetSymbolAddress((void**)&vbuf, g_vbuf);
    cudaGetSymbolAddress((void**)&attn, g_attn);

    // QKV projections: C = X * W^T
    sgemm_abt<<<dim3(QDIM / 128, MROWS / 128), 256>>>(x, Wq, qbuf, MROWS, QDIM, HID);
    sgemm_abt<<<dim3(KDIM / 128, MROWS / 128), 256>>>(x, Wk, kbuf, MROWS, KDIM, HID);
    sgemm_abt<<<dim3(KDIM / 128, MROWS / 128), 256>>>(x, Wv, vbuf, MROWS, KDIM, HID);

    // RMSNorm + RoPE + transpose: one warp per (b,s,head-vector)
    normrope_kernel<<<(MROWS * 32) / 8, 256>>>(cosb, sinb, qw, kw);

    // Causal flash attention
    flash_kernel<<<dim3(Ss / 64, NH, Bb), 256>>>();

    // Output projection: C = attn * Wo^T
    sgemm_abt<<<dim3(HID / 128, MROWS / 128), 256>>>(attn, Wo, out, MROWS, HID, QDIM);
}

// round 3
// speedup vs baseline: 1.3652x; 1.3652x over previous
#include <cuda_runtime.h>
#include <cuda_bf16.h>
#include <cstdint>

// Problem constants
#define Bb   2
#define Ss   2048
#define HID  1024
#define NH   16
#define NKV  8
#define HD   128
#define MROWS (Bb*Ss)          // 4096
#define QDIM (NH*HD)           // 2048
#define KDIM (NKV*HD)          // 1024
#define SCALE 0.08838834764831845f

// ---------------------------------------------------------------------------
// Scratch (static device memory; no allocation APIs)
// ---------------------------------------------------------------------------
__device__ float g_qbuf[(size_t)MROWS * QDIM];
__device__ float g_kbuf[(size_t)MROWS * KDIM];
__device__ float g_vbuf[(size_t)MROWS * KDIM];
__device__ float g_qT[(size_t)Bb * NH * Ss * HD];
__device__ float g_kT[(size_t)Bb * NKV * Ss * HD];
__device__ float g_vT[(size_t)Bb * NKV * Ss * HD];
__device__ float g_attn[(size_t)MROWS * QDIM];     // tf32-rounded by flash epilogue
// tf32-rounded operand copies
__device__ float g_xT32[(size_t)MROWS * HID];
__device__ float g_wqT32[(size_t)QDIM * HID];
__device__ float g_wkT32[(size_t)KDIM * HID];
__device__ float g_wvT32[(size_t)KDIM * HID];
__device__ float g_woT32[(size_t)HID * QDIM];

// ---------------------------------------------------------------------------
// tf32 pre-rounding (elementwise, float4)
// ---------------------------------------------------------------------------
__global__ __launch_bounds__(256) void cvt_tf32_kernel(const float* __restrict__ src,
                                                       float* __restrict__ dst, int n) {
    int i = (blockIdx.x * 256 + threadIdx.x) * 4;
    if (i < n) {
        float4 v = *(const float4*)(src + i);
        asm("cvt.rna.tf32.f32 %0, %0;" : "+f"(v.x));
        asm("cvt.rna.tf32.f32 %0, %0;" : "+f"(v.y));
        asm("cvt.rna.tf32.f32 %0, %0;" : "+f"(v.z));
        asm("cvt.rna.tf32.f32 %0, %0;" : "+f"(v.w));
        *(float4*)(dst + i) = v;
    }
}

// ---------------------------------------------------------------------------
// mma.sync tf32 GEMM: C[M][N] = A[M][K] * B[N][K]^T   (both K-contiguous)
// BM=128, BN=128, BK=32, 256 threads (8 warps, 4x2), warp tile 32x64.
// Double-buffered cp.async. smem row stride 36 floats -> conflict-free
// tf32 fragment loads (bank = (4*row + col) % 32 is a bijection over the warp).
// ---------------------------------------------------------------------------
#define GPAD 36
#define TILE_F (128 * GPAD)                 // floats per tile
#define TILE_B (TILE_F * 4)                 // 18432 bytes
#define GSM_TOTAL (4 * TILE_B)              // 73728: [A0][A1][B0][B1]

__device__ __forceinline__ void mma_tf32(float* c, const uint32_t* a, const uint32_t* b) {
    asm volatile(
        "mma.sync.aligned.m16n8k8.row.col.f32.tf32.tf32.f32 "
        "{%0,%1,%2,%3}, {%4,%5,%6,%7}, {%8,%9}, {%0,%1,%2,%3};"
        : "+f"(c[0]), "+f"(c[1]), "+f"(c[2]), "+f"(c[3])
        : "r"(a[0]), "r"(a[1]), "r"(a[2]), "r"(a[3]), "r"(b[0]), "r"(b[1]));
}

__global__ __launch_bounds__(256, 2) void gemm_tf32(const float* __restrict__ A,
                                                    const float* __restrict__ B,
                                                    float* __restrict__ C,
                                                    int M, int N, int K) {
    extern __shared__ float smem[];
    float* As = smem;                 // [2][128][36]
    float* Bs = smem + 2 * TILE_F;    // [2][128][36]

    const int tid  = threadIdx.x;
    const int warp = tid >> 5;
    const int lid  = tid & 31;
    const int wm = (warp >> 1) * 32;  // warp m offset (0,32,64,96)
    const int wn = (warp & 1) * 64;   // warp n offset (0,64)
    const int fr = lid >> 2;          // fragment row 0..7
    const int fc = lid & 3;           // fragment col 0..3

    const int r0 = blockIdx.y * 128;
    const int c0 = blockIdx.x * 128;
    const int T  = K >> 5;

    float acc[2][8][4];
#pragma unroll
    for (int mi = 0; mi < 2; mi++)
#pragma unroll
        for (int ni = 0; ni < 8; ni++)
#pragma unroll
            for (int j = 0; j < 4; j++) acc[mi][ni][j] = 0.f;

    // cp.async tile loader: 1024 16B chunks per operand, 4 per thread
    auto load_tile = [&](int t, int s) {
        float* Ad = As + s * TILE_F;
        float* Bd = Bs + s * TILE_F;
        const float* Ap = A + (size_t)r0 * K + t * 32;
        const float* Bp = B + (size_t)c0 * K + t * 32;
#pragma unroll
        for (int i = 0; i < 4; i++) {
            int ch = tid + i * 256;
            int row = ch >> 3, kc = ch & 7;
            uint32_t da, db;
            asm("{ .reg .u64 t; cvta.to.shared.u64 t, %1; cvt.u32.u64 %0, t; }"
                : "=r"(da) : "l"(Ad + row * GPAD + kc * 4));
            asm("{ .reg .u64 t; cvta.to.shared.u64 t, %1; cvt.u32.u64 %0, t; }"
                : "=r"(db) : "l"(Bd + row * GPAD + kc * 4));
            asm volatile("cp.async.cg.shared.global [%0], [%1], 16;"
                         :: "r"(da), "l"(Ap + (size_t)row * K + kc * 4));
            asm volatile("cp.async.cg.shared.global [%0], [%1], 16;"
                         :: "r"(db), "l"(Bp + (size_t)row * K + kc * 4));
        }
        asm volatile("cp.async.commit_group;" ::: "memory");
    };

    load_tile(0, 0);

    for (int t = 0; t < T; t++) {
        int s = t & 1;
        if (t + 1 < T) load_tile(t + 1, s ^ 1);
        if (t + 1 < T) asm volatile("cp.async.wait_group 1;" ::: "memory");
        else           asm volatile("cp.async.wait_group 0;" ::: "memory");
        __syncthreads();

        const float* Af = As + s * TILE_F;
        const float* Bf = Bs + s * TILE_F;
#pragma unroll
        for (int k8 = 0; k8 < 4; k8++) {
            uint32_t a[2][4], b[8][2];
#pragma unroll
            for (int mi = 0; mi < 2; mi++) {
                const float* p = Af + (wm + mi * 16 + fr) * GPAD + k8 * 8 + fc;
                a[mi][0] = __float_as_uint(p[0]);
                a[mi][1] = __float_as_uint(p[8 * GPAD]);
                a[mi][2] = __float_as_uint(p[4]);
                a[mi][3] = __float_as_uint(p[8 * GPAD + 4]);
            }
#pragma unroll
            for (int ni = 0; ni < 8; ni++) {
                const float* p = Bf + (wn + ni * 8 + fr) * GPAD + k8 * 8 + fc;
                b[ni][0] = __float_as_uint(p[0]);
                b[ni][1] = __float_as_uint(p[4]);
            }
#pragma unroll
            for (int mi = 0; mi < 2; mi++)
#pragma unroll
                for (int ni = 0; ni < 8; ni++)
                    mma_tf32(acc[mi][ni], a[mi], b[ni]);
        }
        __syncthreads();
    }

    // Epilogue: direct STG.64 (each 4-lane group writes a contiguous 32B sector)
#pragma unroll
    for (int mi = 0; mi < 2; mi++) {
        int row = r0 + wm + mi * 16 + fr;
        float* cp0 = C + (size_t)row * N + c0 + wn + fc * 2;
        float* cp1 = C + (size_t)(row + 8) * N + c0 + wn + fc * 2;
#pragma unroll
        for (int ni = 0; ni < 8; ni++) {
            *(float2*)(cp0 + ni * 8) = make_float2(acc[mi][ni][0], acc[mi][ni][1]);
            *(float2*)(cp1 + ni * 8) = make_float2(acc[mi][ni][2], acc[mi][ni][3]);
        }
    }
}

// ---------------------------------------------------------------------------
// RMSNorm + RoPE + transpose (unchanged)
// ---------------------------------------------------------------------------
__global__ __launch_bounds__(256) void normrope_kernel(const float* __restrict__ cosb,
                                                       const float* __restrict__ sinb,
                                                       const float* __restrict__ qw,
                                                       const float* __restrict__ kw) {
    int gwarp = (blockIdx.x * blockDim.x + threadIdx.x) >> 5;
    int lane = threadIdx.x & 31;
    int row = gwarp >> 5;
    int hh  = gwarp & 31;
    int b = row >> 11;
    int s = row & 2047;

    const float* src;
    float* dst;
    const float* w = qw;
    bool dorm = true;
    if (hh < 16) {
        src = g_qbuf + (size_t)row * QDIM + hh * HD;
        dst = g_qT + (((size_t)b * NH + hh) * Ss + s) * HD;
        w = qw;
    } else if (hh < 24) {
        int h = hh - 16;
        src = g_kbuf + (size_t)row * KDIM + h * HD;
        dst = g_kT + (((size_t)b * NKV + h) * Ss + s) * HD;
        w = kw;
    } else {
        int h = hh - 24;
        src = g_vbuf + (size_t)row * KDIM + h * HD;
        dst = g_vT + (((size_t)b * NKV + h) * Ss + s) * HD;
        dorm = false;
    }

    float x0 = src[lane], x1 = src[lane + 32], x2 = src[lane + 64], x3 = src[lane + 96];

    if (dorm) {
        float ss = x0 * x0 + x1 * x1 + x2 * x2 + x3 * x3;
#pragma unroll
        for (int o = 16; o; o >>= 1) ss += __shfl_xor_sync(0xffffffffu, ss, o);
        float inv = rsqrtf(ss * (1.0f / 128.0f) + 1e-6f);
        x0 = x0 * inv * w[lane];
        x1 = x1 * inv * w[lane + 32];
        x2 = x2 * inv * w[lane + 64];
        x3 = x3 * inv * w[lane + 96];
        const float* cp = cosb + (size_t)row * HD;
        const float* sp = sinb + (size_t)row * HD;
        float c0 = cp[lane], c1 = cp[lane + 32], c2 = cp[lane + 64], c3 = cp[lane + 96];
        float s0 = sp[lane], s1 = sp[lane + 32], s2 = sp[lane + 64], s3 = sp[lane + 96];
        float y0 = x0 * c0 - x2 * s0;
        float y1 = x1 * c1 - x3 * s1;
        float y2 = x2 * c2 + x0 * s2;
        float y3 = x3 * c3 + x1 * s3;
        x0 = y0; x1 = y1; x2 = y2; x3 = y3;
    }

    dst[lane] = x0; dst[lane + 32] = x1; dst[lane + 64] = x2; dst[lane + 96] = x3;
}

// ---------------------------------------------------------------------------
// fp32 flash attention (unchanged; tf32-rounded output feeds O-proj mma)
// ---------------------------------------------------------------------------
__global__ __launch_bounds__(256) void flash_kernel() {
    int tid = threadIdx.x;
    int m   = tid >> 2;
    int sub = tid & 3;
    int q0 = blockIdx.x * 64;
    int h  = blockIdx.y;
    int b  = blockIdx.z;
    int hk = h >> 1;
    int qglob = q0 + m;

    __shared__ float Ks[32 * 128];
    __shared__ float Vs[32 * 128];

    const float* qptr = g_qT + (((size_t)b * NH + h) * Ss + qglob) * HD;
    float qreg[32], o[32];
#pragma unroll
    for (int i = 0; i < 8; i++) {
        float4 t = *(const float4*)(qptr + sub * 4 + 16 * i);
        qreg[4 * i + 0] = t.x; qreg[4 * i + 1] = t.y;
        qreg[4 * i + 2] = t.z; qreg[4 * i + 3] = t.w;
    }
#pragma unroll
    for (int i = 0; i < 32; i++) o[i] = 0.f;

    float mrow = -1e30f, lrow = 0.f;

    const float* kb = g_kT + (((size_t)b * NKV + hk) * Ss) * HD;
    const float* vb = g_vT + (((size_t)b * NKV + hk) * Ss) * HD;

    int ntiles = (q0 + 64) >> 5;
    for (int t = 0; t < ntiles; t++) {
        int n0 = t * 32;
        const float4* ksrc = (const float4*)(kb + (size_t)n0 * HD);
        const float4* vsrc = (const float4*)(vb + (size_t)n0 * HD);
        float4* kd = (float4*)Ks;
        float4* vd = (float4*)Vs;
#pragma unroll
        for (int r = 0; r < 4; r++) {
            int lin = tid + r * 256;
            kd[lin] = ksrc[lin];
            vd[lin] = vsrc[lin];
        }
        __syncthreads();

        float sv[32];
        const float4* K4 = (const float4*)Ks;
#pragma unroll
        for (int n = 0; n < 32; n++) {
            const float4* kp = K4 + n * 32 + sub;
            float d0 = 0.f, d1 = 0.f, d2 = 0.f, d3 = 0.f;
#pragma unroll
            for (int i = 0; i < 8; i++) {
                float4 kv = kp[4 * i];
                d0 += qreg[4 * i + 0] * kv.x;
                d1 += qreg[4 * i + 1] * kv.y;
                d2 += qreg[4 * i + 2] * kv.z;
                d3 += qreg[4 * i + 3] * kv.w;
            }
            float dot = (d0 + d1) + (d2 + d3);
            dot += __shfl_xor_sync(0xffffffffu, dot, 1);
            dot += __shfl_xor_sync(0xffffffffu, dot, 2);
            float sc = dot * SCALE;
            if (n0 + n > qglob) sc = -1e9f;
            sv[n] = sc;
        }

        float tmax = sv[0];
#pragma unroll
        for (int n = 1; n < 32; n++) tmax = fmaxf(tmax, sv[n]);
        float mnew = fmaxf(mrow, tmax);
        float corr = __expf(mrow - mnew);
        lrow *= corr;
#pragma unroll
        for (int i = 0; i < 32; i++) o[i] *= corr;

        const float4* V4 = (const float4*)Vs;
#pragma unroll
        for (int n = 0; n < 32; n++) {
            float p = __expf(sv[n] - mnew);
            lrow += p;
            const float4* vp = V4 + n * 32 + sub;
#pragma unroll
            for (int i = 0; i < 8; i++) {
                float4 vv = vp[4 * i];
                o[4 * i + 0] += p * vv.x;
                o[4 * i + 1] += p * vv.y;
                o[4 * i + 2] += p * vv.z;
                o[4 * i + 3] += p * vv.w;
            }
        }
        mrow = mnew;
        __syncthreads();
    }

    float inv = 1.0f / lrow;
    float* ob = g_attn + ((size_t)(b * Ss + qglob) * NH + h) * HD;
#pragma unroll
    for (int i = 0; i < 8; i++) {
        float a0 = o[4 * i + 0] * inv, a1 = o[4 * i + 1] * inv;
        float a2 = o[4 * i + 2] * inv, a3 = o[4 * i + 3] * inv;
        asm("cvt.rna.tf32.f32 %0, %0;" : "+f"(a0));
        asm("cvt.rna.tf32.f32 %0, %0;" : "+f"(a1));
        asm("cvt.rna.tf32.f32 %0, %0;" : "+f"(a2));
        asm("cvt.rna.tf32.f32 %0, %0;" : "+f"(a3));
        float4 v = make_float4(a0, a1, a2, a3);
        *(float4*)(ob + sub * 4 + 16 * i) = v;
    }
}

// ---------------------------------------------------------------------------
extern "C" void kernel_launch(void* const* d_in, const int* in_sizes, int n_in,
                              void* d_out, int out_size) {
    const float* x    = (const float*)d_in[0];
    const float* cosb = (const float*)d_in[1];
    const float* sinb = (const float*)d_in[2];
    const float* Wq = (const float*)d_in[4];
    const float* Wk = (const float*)d_in[5];
    const float* Wv = (const float*)d_in[6];
    const float* Wo = (const float*)d_in[7];
    const float* qw = (const float*)d_in[8];
    const float* kw = (const float*)d_in[9];
    float* out = (float*)d_out;

    float *qbuf, *kbuf, *vbuf, *attn;
    float *xT, *wqT, *wkT, *wvT, *woT;
    cudaGetSymbolAddress((void**)&qbuf, g_qbuf);
    cudaGetSymbolAddress((void**)&kbuf, g_kbuf);
    cudaGetSymbolAddress((void**)&vbuf, g_vbuf);
    cudaGetSymbolAddress((void**)&attn, g_attn);
    cudaGetSymbolAddress((void**)&xT,  g_xT32);
    cudaGetSymbolAddress((void**)&wqT, g_wqT32);
    cudaGetSymbolAddress((void**)&wkT, g_wkT32);
    cudaGetSymbolAddress((void**)&wvT, g_wvT32);
    cudaGetSymbolAddress((void**)&woT, g_woT32);

    cudaFuncSetAttribute(gemm_tf32, cudaFuncAttributeMaxDynamicSharedMemorySize, GSM_TOTAL);

    // tf32 pre-rounding of GEMM operands
    cvt_tf32_kernel<<<(MROWS * HID) / 1024, 256>>>(x,  xT,  MROWS * HID);
    cvt_tf32_kernel<<<(QDIM * HID) / 1024, 256>>>(Wq, wqT, QDIM * HID);
    cvt_tf32_kernel<<<(KDIM * HID) / 1024, 256>>>(Wk, wkT, KDIM * HID);
    cvt_tf32_kernel<<<(KDIM * HID) / 1024, 256>>>(Wv, wvT, KDIM * HID);
    cvt_tf32_kernel<<<(HID * QDIM) / 1024, 256>>>(Wo, woT, HID * QDIM);

    // QKV projections on mma.sync tf32
    gemm_tf32<<<dim3(QDIM / 128, MROWS / 128), 256, GSM_TOTAL>>>(xT, wqT, qbuf, MROWS, QDIM, HID);
    gemm_tf32<<<dim3(KDIM / 128, MROWS / 128), 256, GSM_TOTAL>>>(xT, wkT, kbuf, MROWS, KDIM, HID);
    gemm_tf32<<<dim3(KDIM / 128, MROWS / 128), 256, GSM_TOTAL>>>(xT, wvT, vbuf, MROWS, KDIM, HID);

    // RMSNorm + RoPE + transpose
    normrope_kernel<<<(MROWS * 32) / 8, 256>>>(cosb, sinb, qw, kw);

    // Causal flash attention (fp32, tf32-rounded output)
    flash_kernel<<<dim3(Ss / 64, NH, Bb), 256>>>();

    // Output projection on mma.sync tf32
    gemm_tf32<<<dim3(HID / 128, MROWS / 128), 256, GSM_TOTAL>>>(attn, woT, out, MROWS, HID, QDIM);
}

// round 4
// speedup vs baseline: 4.5956x; 3.3663x over previous
#include <cuda_runtime.h>
#include <cuda_bf16.h>
#include <cstdint>

// Problem constants
#define Bb   2
#define Ss   2048
#define HID  1024
#define NH   16
#define NKV  8
#define HD   128
#define MROWS (Bb*Ss)          // 4096
#define QDIM (NH*HD)           // 2048
#define KDIM (NKV*HD)          // 1024
#define SCALE 0.08838834764831845f

// ---------------------------------------------------------------------------
// Scratch (static device memory; no allocation APIs)
// ---------------------------------------------------------------------------
__device__ float g_qbuf[(size_t)MROWS * QDIM];
__device__ float g_kbuf[(size_t)MROWS * KDIM];
__device__ float g_vbuf[(size_t)MROWS * KDIM];
__device__ float g_qT[(size_t)Bb * NH * Ss * HD];    // [b][h][s][d], tf32-rounded
__device__ float g_kT[(size_t)Bb * NKV * Ss * HD];   // [b][hk][s][d], tf32-rounded
__device__ float g_vT[(size_t)Bb * NKV * Ss * HD];   // [b][hk][d][s] TRANSPOSED, tf32
__device__ float g_attn[(size_t)MROWS * QDIM];       // tf32-rounded by flash epilogue
// tf32-rounded operand copies
__device__ float g_xT32[(size_t)MROWS * HID];
__device__ float g_wqT32[(size_t)QDIM * HID];
__device__ float g_wkT32[(size_t)KDIM * HID];
__device__ float g_wvT32[(size_t)KDIM * HID];
__device__ float g_woT32[(size_t)HID * QDIM];

__device__ __forceinline__ float tf32r(float x) {
    asm("cvt.rna.tf32.f32 %0, %0;" : "+f"(x));
    return x;
}
__device__ __forceinline__ uint32_t s2u(const void* p) {
    uint32_t a;
    asm("{ .reg .u64 t; cvta.to.shared.u64 t, %1; cvt.u32.u64 %0, t; }" : "=r"(a) : "l"(p));
    return a;
}
__device__ __forceinline__ void cpasync16(uint32_t dst, const void* src) {
    asm volatile("cp.async.cg.shared.global [%0], [%1], 16;" :: "r"(dst), "l"(src));
}
__device__ __forceinline__ void mma_tf32(float* c, const uint32_t* a, const uint32_t* b) {
    asm volatile(
        "mma.sync.aligned.m16n8k8.row.col.f32.tf32.tf32.f32 "
        "{%0,%1,%2,%3}, {%4,%5,%6,%7}, {%8,%9}, {%0,%1,%2,%3};"
        : "+f"(c[0]), "+f"(c[1]), "+f"(c[2]), "+f"(c[3])
        : "r"(a[0]), "r"(a[1]), "r"(a[2]), "r"(a[3]), "r"(b[0]), "r"(b[1]));
}

// ---------------------------------------------------------------------------
// tf32 pre-rounding (elementwise, float4)
// ---------------------------------------------------------------------------
__global__ __launch_bounds__(256) void cvt_tf32_kernel(const float* __restrict__ src,
                                                       float* __restrict__ dst, int n) {
    int i = (blockIdx.x * 256 + threadIdx.x) * 4;
    if (i < n) {
        float4 v = *(const float4*)(src + i);
        v.x = tf32r(v.x); v.y = tf32r(v.y); v.z = tf32r(v.z); v.w = tf32r(v.w);
        *(float4*)(dst + i) = v;
    }
}

// ---------------------------------------------------------------------------
// mma.sync tf32 GEMM: C[M][N] = A[M][K] * B[N][K]^T  (unchanged from R3)
// ---------------------------------------------------------------------------
#define GPAD 36
#define TILE_F (128 * GPAD)
#define GSM_TOTAL (4 * TILE_F * 4)

__global__ __launch_bounds__(256, 2) void gemm_tf32(const float* __restrict__ A,
                                                    const float* __restrict__ B,
                                                    float* __restrict__ C,
                                                    int M, int N, int K) {
    extern __shared__ float smem[];
    float* As = smem;
    float* Bs = smem + 2 * TILE_F;

    const int tid  = threadIdx.x;
    const int warp = tid >> 5;
    const int lid  = tid & 31;
    const int wm = (warp >> 1) * 32;
    const int wn = (warp & 1) * 64;
    const int fr = lid >> 2;
    const int fc = lid & 3;

    const int r0 = blockIdx.y * 128;
    const int c0 = blockIdx.x * 128;
    const int T  = K >> 5;

    float acc[2][8][4];
#pragma unroll
    for (int mi = 0; mi < 2; mi++)
#pragma unroll
        for (int ni = 0; ni < 8; ni++)
#pragma unroll
            for (int j = 0; j < 4; j++) acc[mi][ni][j] = 0.f;

    auto load_tile = [&](int t, int s) {
        float* Ad = As + s * TILE_F;
        float* Bd = Bs + s * TILE_F;
        const float* Ap = A + (size_t)r0 * K + t * 32;
        const float* Bp = B + (size_t)c0 * K + t * 32;
#pragma unroll
        for (int i = 0; i < 4; i++) {
            int ch = tid + i * 256;
            int row = ch >> 3, kc = ch & 7;
            cpasync16(s2u(Ad + row * GPAD + kc * 4), Ap + (size_t)row * K + kc * 4);
            cpasync16(s2u(Bd + row * GPAD + kc * 4), Bp + (size_t)row * K + kc * 4);
        }
        asm volatile("cp.async.commit_group;" ::: "memory");
    };

    load_tile(0, 0);

    for (int t = 0; t < T; t++) {
        int s = t & 1;
        if (t + 1 < T) load_tile(t + 1, s ^ 1);
        if (t + 1 < T) asm volatile("cp.async.wait_group 1;" ::: "memory");
        else           asm volatile("cp.async.wait_group 0;" ::: "memory");
        __syncthreads();

        const float* Af = As + s * TILE_F;
        const float* Bf = Bs + s * TILE_F;
#pragma unroll
        for (int k8 = 0; k8 < 4; k8++) {
            uint32_t a[2][4], b[8][2];
#pragma unroll
            for (int mi = 0; mi < 2; mi++) {
                const float* p = Af + (wm + mi * 16 + fr) * GPAD + k8 * 8 + fc;
                a[mi][0] = __float_as_uint(p[0]);
                a[mi][1] = __float_as_uint(p[8 * GPAD]);
                a[mi][2] = __float_as_uint(p[4]);
                a[mi][3] = __float_as_uint(p[8 * GPAD + 4]);
            }
#pragma unroll
            for (int ni = 0; ni < 8; ni++) {
                const float* p = Bf + (wn + ni * 8 + fr) * GPAD + k8 * 8 + fc;
                b[ni][0] = __float_as_uint(p[0]);
                b[ni][1] = __float_as_uint(p[4]);
            }
#pragma unroll
            for (int mi = 0; mi < 2; mi++)
#pragma unroll
                for (int ni = 0; ni < 8; ni++)
                    mma_tf32(acc[mi][ni], a[mi], b[ni]);
        }
        __syncthreads();
    }

#pragma unroll
    for (int mi = 0; mi < 2; mi++) {
        int row = r0 + wm + mi * 16 + fr;
        float* cp0 = C + (size_t)row * N + c0 + wn + fc * 2;
        float* cp1 = C + (size_t)(row + 8) * N + c0 + wn + fc * 2;
#pragma unroll
        for (int ni = 0; ni < 8; ni++) {
            *(float2*)(cp0 + ni * 8) = make_float2(acc[mi][ni][0], acc[mi][ni][1]);
            *(float2*)(cp1 + ni * 8) = make_float2(acc[mi][ni][2], acc[mi][ni][3]);
        }
    }
}

// ---------------------------------------------------------------------------
// RMSNorm + RoPE + transpose. Q/K tf32-rounded; V tf32-rounded AND stored
// d-major ([b][hk][d][s]) for the PV mma B operand.
// ---------------------------------------------------------------------------
__global__ __launch_bounds__(256) void normrope_kernel(const float* __restrict__ cosb,
                                                       const float* __restrict__ sinb,
                                                       const float* __restrict__ qw,
                                                       const float* __restrict__ kw) {
    int gwarp = (blockIdx.x * blockDim.x + threadIdx.x) >> 5;
    int lane = threadIdx.x & 31;
    int row = gwarp >> 5;
    int hh  = gwarp & 31;
    int b = row >> 11;
    int s = row & 2047;

    if (hh >= 24) {
        // V: copy with transpose + tf32 rounding
        int h = hh - 24;
        const float* src = g_vbuf + (size_t)row * KDIM + h * HD;
        float* dst = g_vT + ((size_t)b * NKV + h) * Ss * HD;
        float x0 = tf32r(src[lane]);
        float x1 = tf32r(src[lane + 32]);
        float x2 = tf32r(src[lane + 64]);
        float x3 = tf32r(src[lane + 96]);
        dst[(size_t)(lane)      * Ss + s] = x0;
        dst[(size_t)(lane + 32) * Ss + s] = x1;
        dst[(size_t)(lane + 64) * Ss + s] = x2;
        dst[(size_t)(lane + 96) * Ss + s] = x3;
        return;
    }

    const float* src;
    float* dst;
    const float* w;
    if (hh < 16) {
        src = g_qbuf + (size_t)row * QDIM + hh * HD;
        dst = g_qT + (((size_t)b * NH + hh) * Ss + s) * HD;
        w = qw;
    } else {
        int h = hh - 16;
        src = g_kbuf + (size_t)row * KDIM + h * HD;
        dst = g_kT + (((size_t)b * NKV + h) * Ss + s) * HD;
        w = kw;
    }

    float x0 = src[lane], x1 = src[lane + 32], x2 = src[lane + 64], x3 = src[lane + 96];

    float ss = x0 * x0 + x1 * x1 + x2 * x2 + x3 * x3;
#pragma unroll
    for (int o = 16; o; o >>= 1) ss += __shfl_xor_sync(0xffffffffu, ss, o);
    float inv = rsqrtf(ss * (1.0f / 128.0f) + 1e-6f);
    x0 = x0 * inv * w[lane];
    x1 = x1 * inv * w[lane + 32];
    x2 = x2 * inv * w[lane + 64];
    x3 = x3 * inv * w[lane + 96];
    const float* cp = cosb + (size_t)row * HD;
    const float* sp = sinb + (size_t)row * HD;
    float c0 = cp[lane], c1 = cp[lane + 32], c2 = cp[lane + 64], c3 = cp[lane + 96];
    float s0 = sp[lane], s1 = sp[lane + 32], s2 = sp[lane + 64], s3 = sp[lane + 96];
    float y0 = x0 * c0 - x2 * s0;
    float y1 = x1 * c1 - x3 * s1;
    float y2 = x2 * c2 + x0 * s2;
    float y3 = x3 * c3 + x1 * s3;

    dst[lane]      = tf32r(y0);
    dst[lane + 32] = tf32r(y1);
    dst[lane + 64] = tf32r(y2);
    dst[lane + 96] = tf32r(y3);
}

// ---------------------------------------------------------------------------
// Tensorized flash attention (tf32 mma), causal, GQA.
// BM=64 q, BN=64 kv, 256 threads (8 warps 4x2). Double-buffered cp.async.
// smem (floats): Qs[64*132] | Ks[2][64*132] | Vt[2][128*68] | Ssc[64*68]
//              | corr[64] | linv[64]
// ---------------------------------------------------------------------------
#define FQ_PITCH 132
#define FV_PITCH 68
#define FS_PITCH 68
#define OFF_KS   (64 * FQ_PITCH)                 // 8448
#define OFF_VT   (OFF_KS + 2 * 64 * FQ_PITCH)    // 25344
#define OFF_SS   (OFF_VT + 2 * 128 * FV_PITCH)   // 42752
#define OFF_CORR (OFF_SS + 64 * FS_PITCH)        // 47104
#define OFF_LINV (OFF_CORR + 64)
#define FSM_TOTAL ((OFF_LINV + 64) * 4)          // 188928 bytes

__global__ __launch_bounds__(256, 1) void flash_mma_kernel() {
    extern __shared__ float fs[];
    float* Qs   = fs;
    float* Ksb  = fs + OFF_KS;
    float* Vtb  = fs + OFF_VT;
    float* Ssc  = fs + OFF_SS;
    float* corr = fs + OFF_CORR;
    float* linv = fs + OFF_LINV;

    const int tid  = threadIdx.x;
    const int warp = tid >> 5;
    const int lid  = tid & 31;
    const int fr = lid >> 2;
    const int fc = lid & 3;
    const int wmS = (warp >> 1) * 16;   // S-phase warp m offset
    const int wnS = (warp & 1) * 32;    // S-phase warp n offset
    const int wmO = wmS;                // O-phase warp m offset
    const int wnO = (warp & 1) * 64;    // O-phase warp n (head dim) offset

    const int q0 = blockIdx.x * 64;
    const int h  = blockIdx.y;
    const int b  = blockIdx.z;
    const int hk = h >> 1;

    const float* qb  = g_qT + (((size_t)b * NH + h) * Ss + q0) * HD;
    const float* kb  = g_kT + ((size_t)b * NKV + hk) * Ss * HD;
    const float* vtb = g_vT + ((size_t)b * NKV + hk) * Ss * HD;  // [d][s]

    // softmax state: this thread owns score row (tid>>2), column group (tid&3)
    const int srow = tid >> 2;
    const int ssub = tid & 3;
    float m_old = -1e30f, l_old = 0.f;

    float oa[8][4];
#pragma unroll
    for (int nf = 0; nf < 8; nf++)
#pragma unroll
        for (int j = 0; j < 4; j++) oa[nf][j] = 0.f;

    auto loadQ = [&]() {
#pragma unroll
        for (int i = 0; i < 8; i++) {
            int ch = tid + i * 256;
            int row = ch >> 5, kc = ch & 31;
            cpasync16(s2u(Qs + row * FQ_PITCH + kc * 4), qb + (size_t)row * HD + kc * 4);
        }
    };
    auto loadK = [&](int j, int s) {
        float* Kd = Ksb + s * 64 * FQ_PITCH;
        const float* src = kb + (size_t)(j * 64) * HD;
#pragma unroll
        for (int i = 0; i < 8; i++) {
            int ch = tid + i * 256;
            int row = ch >> 5, kc = ch & 31;
            cpasync16(s2u(Kd + row * FQ_PITCH + kc * 4), src + (size_t)row * HD + kc * 4);
        }
    };
    auto loadV = [&](int j, int s) {
        float* Vd = Vtb + s * 128 * FV_PITCH;
#pragma unroll
        for (int i = 0; i < 8; i++) {
            int ch = tid + i * 256;
            int row = ch >> 4, kc = ch & 15;     // row=d 0..127, 16 chunks of 16B
            cpasync16(s2u(Vd + row * FV_PITCH + kc * 4), vtb + (size_t)row * Ss + j * 64 + kc * 4);
        }
    };

    const int nt = blockIdx.x + 1;
    loadQ(); loadK(0, 0); loadV(0, 0);
    asm volatile("cp.async.commit_group;" ::: "memory");

    for (int j = 0; j < nt; j++) {
        int s = j & 1;
        if (j + 1 < nt) {
            loadK(j + 1, s ^ 1); loadV(j + 1, s ^ 1);
            asm volatile("cp.async.commit_group;" ::: "memory");
            asm volatile("cp.async.wait_group 1;" ::: "memory");
        } else {
            asm volatile("cp.async.wait_group 0;" ::: "memory");
        }
        __syncthreads();

        // ---- S = Q K^T (warp tile 16x32) ----
        const float* Kf = Ksb + s * 64 * FQ_PITCH;
        float sa[4][4];
#pragma unroll
        for (int nf = 0; nf < 4; nf++)
#pragma unroll
            for (int t = 0; t < 4; t++) sa[nf][t] = 0.f;
#pragma unroll
        for (int k8 = 0; k8 < 16; k8++) {
            uint32_t a[4], bfr[4][2];
            const float* ap = Qs + (wmS + fr) * FQ_PITCH + k8 * 8 + fc;
            a[0] = __float_as_uint(ap[0]);
            a[1] = __float_as_uint(ap[8 * FQ_PITCH]);
            a[2] = __float_as_uint(ap[4]);
            a[3] = __float_as_uint(ap[8 * FQ_PITCH + 4]);
#pragma unroll
            for (int nf = 0; nf < 4; nf++) {
                const float* bp = Kf + (wnS + nf * 8 + fr) * FQ_PITCH + k8 * 8 + fc;
                bfr[nf][0] = __float_as_uint(bp[0]);
                bfr[nf][1] = __float_as_uint(bp[4]);
            }
#pragma unroll
            for (int nf = 0; nf < 4; nf++) mma_tf32(sa[nf], a, bfr[nf]);
        }
        // stage S fragments to smem
#pragma unroll
        for (int nf = 0; nf < 4; nf++) {
            int col = wnS + nf * 8 + 2 * fc;
            *(float2*)&Ssc[(wmS + fr) * FS_PITCH + col]     = make_float2(sa[nf][0], sa[nf][1]);
            *(float2*)&Ssc[(wmS + fr + 8) * FS_PITCH + col] = make_float2(sa[nf][2], sa[nf][3]);
        }
        __syncthreads();

        // ---- online softmax (4 threads per row) ----
        {
            float sv[16];
            float mx = -1e30f;
            int qglob = q0 + srow;
#pragma unroll
            for (int i = 0; i < 16; i++) {
                int c = ssub + 4 * i;
                float val = Ssc[srow * FS_PITCH + c] * SCALE;
                if (j * 64 + c > qglob) val = -1e9f;
                sv[i] = val;
                mx = fmaxf(mx, val);
            }
            mx = fmaxf(mx, __shfl_xor_sync(0xffffffffu, mx, 1));
            mx = fmaxf(mx, __shfl_xor_sync(0xffffffffu, mx, 2));
            float mnew = fmaxf(m_old, mx);
            float cr = __expf(m_old - mnew);
            float psum = 0.f;
#pragma unroll
            for (int i = 0; i < 16; i++) {
                float p = __expf(sv[i] - mnew);
                psum += p;
                Ssc[srow * FS_PITCH + ssub + 4 * i] = tf32r(p);
            }
            psum += __shfl_xor_sync(0xffffffffu, psum, 1);
            psum += __shfl_xor_sync(0xffffffffu, psum, 2);
            l_old = l_old * cr + psum;
            m_old = mnew;
            if (ssub == 0) corr[srow] = cr;
        }
        __syncthreads();

        // ---- O = O*corr + P V (warp tile 16x64) ----
        const float* Vf = Vtb + s * 128 * FV_PITCH;
        {
            float cr0 = corr[wmO + fr];
            float cr1 = corr[wmO + fr + 8];
#pragma unroll
            for (int nf = 0; nf < 8; nf++) {
                oa[nf][0] *= cr0; oa[nf][1] *= cr0;
                oa[nf][2] *= cr1; oa[nf][3] *= cr1;
            }
        }
#pragma unroll
        for (int k8 = 0; k8 < 8; k8++) {
            uint32_t a[4], bfr[8][2];
            const float* ap = Ssc + (wmO + fr) * FS_PITCH + k8 * 8 + fc;
            a[0] = __float_as_uint(ap[0]);
            a[1] = __float_as_uint(ap[8 * FS_PITCH]);
            a[2] = __float_as_uint(ap[4]);
            a[3] = __float_as_uint(ap[8 * FS_PITCH + 4]);
#pragma unroll
            for (int nf = 0; nf < 8; nf++) {
                const float* bp = Vf + (wnO + nf * 8 + fr) * FV_PITCH + k8 * 8 + fc;
                bfr[nf][0] = __float_as_uint(bp[0]);
                bfr[nf][1] = __float_as_uint(bp[4]);
            }
#pragma unroll
            for (int nf = 0; nf < 8; nf++) mma_tf32(oa[nf], a, bfr[nf]);
        }
    }

    if (ssub == 0) linv[srow] = 1.0f / l_old;
    __syncthreads();

    // ---- epilogue: normalize, tf32-round, store to g_attn ----
    float i0 = linv[wmO + fr];
    float i1 = linv[wmO + fr + 8];
    int row0 = q0 + wmO + fr;
    float* d0 = g_attn + ((size_t)(b * Ss + row0) * NH + h) * HD + wnO + 2 * fc;
    float* d1 = g_attn + ((size_t)(b * Ss + row0 + 8) * NH + h) * HD + wnO + 2 * fc;
#pragma unroll
    for (int nf = 0; nf < 8; nf++) {
        *(float2*)(d0 + nf * 8) = make_float2(tf32r(oa[nf][0] * i0), tf32r(oa[nf][1] * i0));
        *(float2*)(d1 + nf * 8) = make_float2(tf32r(oa[nf][2] * i1), tf32r(oa[nf][3] * i1));
    }
}

// ---------------------------------------------------------------------------
extern "C" void kernel_launch(void* const* d_in, const int* in_sizes, int n_in,
                              void* d_out, int out_size) {
    const float* x    = (const float*)d_in[0];
    const float* cosb = (const float*)d_in[1];
    const float* sinb = (const float*)d_in[2];
    const float* Wq = (const float*)d_in[4];
    const float* Wk = (const float*)d_in[5];
    const float* Wv = (const float*)d_in[6];
    const float* Wo = (const float*)d_in[7];
    const float* qw = (const float*)d_in[8];
    const float* kw = (const float*)d_in[9];
    float* out = (float*)d_out;

    float *qbuf, *kbuf, *vbuf, *attn;
    float *xT, *wqT, *wkT, *wvT, *woT;
    cudaGetSymbolAddress((void**)&qbuf, g_qbuf);
    cudaGetSymbolAddress((void**)&kbuf, g_kbuf);
    cudaGetSymbolAddress((void**)&vbuf, g_vbuf);
    cudaGetSymbolAddress((void**)&attn, g_attn);
    cudaGetSymbolAddress((void**)&xT,  g_xT32);
    cudaGetSymbolAddress((void**)&wqT, g_wqT32);
    cudaGetSymbolAddress((void**)&wkT, g_wkT32);
    cudaGetSymbolAddress((void**)&wvT, g_wvT32);
    cudaGetSymbolAddress((void**)&woT, g_woT32);

    cudaFuncSetAttribute(gemm_tf32, cudaFuncAttributeMaxDynamicSharedMemorySize, GSM_TOTAL);
    cudaFuncSetAttribute(flash_mma_kernel, cudaFuncAttributeMaxDynamicSharedMemorySize, FSM_TOTAL);

    // tf32 pre-rounding of GEMM operands
    cvt_tf32_kernel<<<(MROWS * HID) / 1024, 256>>>(x,  xT,  MROWS * HID);
    cvt_tf32_kernel<<<(QDIM * HID) / 1024, 256>>>(Wq, wqT, QDIM * HID);
    cvt_tf32_kernel<<<(KDIM * HID) / 1024, 256>>>(Wk, wkT, KDIM * HID);
    cvt_tf32_kernel<<<(KDIM * HID) / 1024, 256>>>(Wv, wvT, KDIM * HID);
    cvt_tf32_kernel<<<(HID * QDIM) / 1024, 256>>>(Wo, woT, HID * QDIM);

    // QKV projections on mma.sync tf32
    gemm_tf32<<<dim3(QDIM / 128, MROWS / 128), 256, GSM_TOTAL>>>(xT, wqT, qbuf, MROWS, QDIM, HID);
    gemm_tf32<<<dim3(KDIM / 128, MROWS / 128), 256, GSM_TOTAL>>>(xT, wkT, kbuf, MROWS, KDIM, HID);
    gemm_tf32<<<dim3(KDIM / 128, MROWS / 128), 256, GSM_TOTAL>>>(xT, wvT, vbuf, MROWS, KDIM, HID);

    // RMSNorm + RoPE + transpose (Q/K tf32; V transposed d-major tf32)
    normrope_kernel<<<(MROWS * 32) / 8, 256>>>(cosb, sinb, qw, kw);

    // Tensorized causal flash attention
    flash_mma_kernel<<<dim3(Ss / 64, NH, Bb), 256, FSM_TOTAL>>>();

    // Output projection on mma.sync tf32
    gemm_tf32<<<dim3(HID / 128, MROWS / 128), 256, GSM_TOTAL>>>(attn, woT, out, MROWS, HID, QDIM);
}

// round 5
// speedup vs baseline: 7.2493x; 1.5775x over previous
#include <cuda_runtime.h>
#include <cuda_fp16.h>
#include <cstdint>

// Problem constants
#define Bb   2
#define Ss   2048
#define HID  1024
#define NH   16
#define NKV  8
#define HD   128
#define MROWS (Bb*Ss)          // 4096
#define QDIM (NH*HD)           // 2048
#define KDIM (NKV*HD)          // 1024
#define SCALE 0.08838834764831845f

// ---------------------------------------------------------------------------
// Scratch (static device memory; no allocation APIs)
// ---------------------------------------------------------------------------
__device__ float  g_qbuf[(size_t)MROWS * QDIM];
__device__ float  g_kbuf[(size_t)MROWS * KDIM];
__device__ float  g_vbuf[(size_t)MROWS * KDIM];
__device__ __half g_qTh[(size_t)Bb * NH * Ss * HD];    // [b][h][s][d]
__device__ __half g_kTh[(size_t)Bb * NKV * Ss * HD];   // [b][hk][s][d]
__device__ __half g_vTh[(size_t)Bb * NKV * Ss * HD];   // [b][hk][d][s] transposed
__device__ __half g_attnH[(size_t)MROWS * QDIM];       // flash output (half)
// fp16 operand copies
__device__ __half g_xH[(size_t)MROWS * HID];
__device__ __half g_wqH[(size_t)QDIM * HID];
__device__ __half g_wkH[(size_t)KDIM * HID];
__device__ __half g_wvH[(size_t)KDIM * HID];
__device__ __half g_woH[(size_t)HID * QDIM];

__device__ __forceinline__ uint32_t s2u(const void* p) {
    uint32_t a;
    asm("{ .reg .u64 t; cvta.to.shared.u64 t, %1; cvt.u32.u64 %0, t; }" : "=r"(a) : "l"(p));
    return a;
}
__device__ __forceinline__ void cpasync16(uint32_t dst, const void* src) {
    asm volatile("cp.async.cg.shared.global [%0], [%1], 16;" :: "r"(dst), "l"(src));
}
__device__ __forceinline__ void mma_f16(float* c, const uint32_t* a, const uint32_t* b) {
    asm volatile(
        "mma.sync.aligned.m16n8k16.row.col.f32.f16.f16.f32 "
        "{%0,%1,%2,%3}, {%4,%5,%6,%7}, {%8,%9}, {%0,%1,%2,%3};"
        : "+f"(c[0]), "+f"(c[1]), "+f"(c[2]), "+f"(c[3])
        : "r"(a[0]), "r"(a[1]), "r"(a[2]), "r"(a[3]), "r"(b[0]), "r"(b[1]));
}
__device__ __forceinline__ uint32_t ldh2(const __half* p) {
    return *(const uint32_t*)p;
}

// ---------------------------------------------------------------------------
// float -> half pack (8 elements/thread)
// ---------------------------------------------------------------------------
__global__ __launch_bounds__(256) void cvt_f2h_kernel(const float* __restrict__ src,
                                                      __half* __restrict__ dst, int n) {
    int i = (blockIdx.x * 256 + threadIdx.x) * 8;
    if (i < n) {
        float4 v0 = *(const float4*)(src + i);
        float4 v1 = *(const float4*)(src + i + 4);
        __half2* d = (__half2*)(dst + i);
        d[0] = __floats2half2_rn(v0.x, v0.y);
        d[1] = __floats2half2_rn(v0.z, v0.w);
        d[2] = __floats2half2_rn(v1.x, v1.y);
        d[3] = __floats2half2_rn(v1.z, v1.w);
    }
}

// ---------------------------------------------------------------------------
// f16 mma GEMM: C[M][N](f32) = A[M][K] * B[N][K]^T   (half, K-contiguous)
// BM=128, BN=128, BK=32, 256 threads (8 warps 4x2), warp tile 32x64.
// smem pitch 72 halves (144B) -> bank = (4*row+fc) mod 32, conflict-free.
// ---------------------------------------------------------------------------
#define GPADH 72
#define TILE_H (128 * GPADH)                // halves per tile (9216)
#define GSM_TOTAL (4 * TILE_H * 2)          // 73728 bytes: [A0][A1][B0][B1]

__global__ __launch_bounds__(256, 2) void gemm_f16(const __half* __restrict__ A,
                                                   const __half* __restrict__ B,
                                                   float* __restrict__ C,
                                                   int M, int N, int K) {
    extern __shared__ __half hsm[];
    __half* As = hsm;
    __half* Bs = hsm + 2 * TILE_H;

    const int tid  = threadIdx.x;
    const int warp = tid >> 5;
    const int lid  = tid & 31;
    const int wm = (warp >> 1) * 32;
    const int wn = (warp & 1) * 64;
    const int fr = lid >> 2;
    const int fc = lid & 3;

    const int r0 = blockIdx.y * 128;
    const int c0 = blockIdx.x * 128;
    const int T  = K >> 5;

    float acc[2][8][4];
#pragma unroll
    for (int mi = 0; mi < 2; mi++)
#pragma unroll
        for (int ni = 0; ni < 8; ni++)
#pragma unroll
            for (int j = 0; j < 4; j++) acc[mi][ni][j] = 0.f;

    auto load_tile = [&](int t, int s) {
        __half* Ad = As + s * TILE_H;
        __half* Bd = Bs + s * TILE_H;
        const __half* Ap = A + (size_t)r0 * K + t * 32;
        const __half* Bp = B + (size_t)c0 * K + t * 32;
#pragma unroll
        for (int i = 0; i < 2; i++) {
            int ch = tid + i * 256;              // 512 chunks of 8 halves
            int row = ch >> 2, kc = ch & 3;
            cpasync16(s2u(Ad + row * GPADH + kc * 8), Ap + (size_t)row * K + kc * 8);
            cpasync16(s2u(Bd + row * GPADH + kc * 8), Bp + (size_t)row * K + kc * 8);
        }
        asm volatile("cp.async.commit_group;" ::: "memory");
    };

    load_tile(0, 0);

    for (int t = 0; t < T; t++) {
        int s = t & 1;
        if (t + 1 < T) load_tile(t + 1, s ^ 1);
        if (t + 1 < T) asm volatile("cp.async.wait_group 1;" ::: "memory");
        else           asm volatile("cp.async.wait_group 0;" ::: "memory");
        __syncthreads();

        const __half* Af = As + s * TILE_H;
        const __half* Bf = Bs + s * TILE_H;
#pragma unroll
        for (int kk = 0; kk < 2; kk++) {
            uint32_t a[2][4], b[8][2];
#pragma unroll
            for (int mi = 0; mi < 2; mi++) {
                const __half* p = Af + (wm + mi * 16 + fr) * GPADH + kk * 16 + 2 * fc;
                a[mi][0] = ldh2(p);
                a[mi][1] = ldh2(p + 8 * GPADH);
                a[mi][2] = ldh2(p + 8);
                a[mi][3] = ldh2(p + 8 * GPADH + 8);
            }
#pragma unroll
            for (int ni = 0; ni < 8; ni++) {
                const __half* p = Bf + (wn + ni * 8 + fr) * GPADH + kk * 16 + 2 * fc;
                b[ni][0] = ldh2(p);
                b[ni][1] = ldh2(p + 8);
            }
#pragma unroll
            for (int mi = 0; mi < 2; mi++)
#pragma unroll
                for (int ni = 0; ni < 8; ni++)
                    mma_f16(acc[mi][ni], a[mi], b[ni]);
        }
        __syncthreads();
    }

#pragma unroll
    for (int mi = 0; mi < 2; mi++) {
        int row = r0 + wm + mi * 16 + fr;
        float* cp0 = C + (size_t)row * N + c0 + wn + fc * 2;
        float* cp1 = C + (size_t)(row + 8) * N + c0 + wn + fc * 2;
#pragma unroll
        for (int ni = 0; ni < 8; ni++) {
            *(float2*)(cp0 + ni * 8) = make_float2(acc[mi][ni][0], acc[mi][ni][1]);
            *(float2*)(cp1 + ni * 8) = make_float2(acc[mi][ni][2], acc[mi][ni][3]);
        }
    }
}

// ---------------------------------------------------------------------------
// RMSNorm + RoPE + transpose -> half outputs.
// V additionally transposed to d-major for the PV mma B operand.
// ---------------------------------------------------------------------------
__global__ __launch_bounds__(256) void normrope_kernel(const float* __restrict__ cosb,
                                                       const float* __restrict__ sinb,
                                                       const float* __restrict__ qw,
                                                       const float* __restrict__ kw) {
    int gwarp = (blockIdx.x * blockDim.x + threadIdx.x) >> 5;
    int lane = threadIdx.x & 31;
    int row = gwarp >> 5;
    int hh  = gwarp & 31;
    int b = row >> 11;
    int s = row & 2047;

    if (hh >= 24) {
        int h = hh - 24;
        const float* src = g_vbuf + (size_t)row * KDIM + h * HD;
        __half* dst = g_vTh + ((size_t)b * NKV + h) * Ss * HD;
        dst[(size_t)(lane)      * Ss + s] = __float2half_rn(src[lane]);
        dst[(size_t)(lane + 32) * Ss + s] = __float2half_rn(src[lane + 32]);
        dst[(size_t)(lane + 64) * Ss + s] = __float2half_rn(src[lane + 64]);
        dst[(size_t)(lane + 96) * Ss + s] = __float2half_rn(src[lane + 96]);
        return;
    }

    const float* src;
    __half* dst;
    const float* w;
    if (hh < 16) {
        src = g_qbuf + (size_t)row * QDIM + hh * HD;
        dst = g_qTh + (((size_t)b * NH + hh) * Ss + s) * HD;
        w = qw;
    } else {
        int h = hh - 16;
        src = g_kbuf + (size_t)row * KDIM + h * HD;
        dst = g_kTh + (((size_t)b * NKV + h) * Ss + s) * HD;
        w = kw;
    }

    float x0 = src[lane], x1 = src[lane + 32], x2 = src[lane + 64], x3 = src[lane + 96];

    float ss = x0 * x0 + x1 * x1 + x2 * x2 + x3 * x3;
#pragma unroll
    for (int o = 16; o; o >>= 1) ss += __shfl_xor_sync(0xffffffffu, ss, o);
    float inv = rsqrtf(ss * (1.0f / 128.0f) + 1e-6f);
    x0 = x0 * inv * w[lane];
    x1 = x1 * inv * w[lane + 32];
    x2 = x2 * inv * w[lane + 64];
    x3 = x3 * inv * w[lane + 96];
    const float* cp = cosb + (size_t)row * HD;
    const float* sp = sinb + (size_t)row * HD;
    float c0 = cp[lane], c1 = cp[lane + 32], c2 = cp[lane + 64], c3 = cp[lane + 96];
    float s0 = sp[lane], s1 = sp[lane + 32], s2 = sp[lane + 64], s3 = sp[lane + 96];

    dst[lane]      = __float2half_rn(x0 * c0 - x2 * s0);
    dst[lane + 32] = __float2half_rn(x1 * c1 - x3 * s1);
    dst[lane + 64] = __float2half_rn(x2 * c2 + x0 * s2);
    dst[lane + 96] = __float2half_rn(x3 * c3 + x1 * s3);
}

// ---------------------------------------------------------------------------
// fp16 tensorized flash attention, causal, GQA.
// BM=64, BN=64, 256 threads (8 warps 4x2). Double-buffered cp.async.
// Half region: Qs[64*136] | Ks[2][64*136] | Vt[2][128*72] | Ps[64*72]
// Float region: Ssc[64*68] | corr[64] | linv[64]
// ---------------------------------------------------------------------------
#define FQP 136                              // Q/K pitch (halves)
#define FVP 72                               // V / P pitch (halves)
#define FSP 68                               // S pitch (floats)
#define HOFF_KS   (64 * FQP)                 // 8704
#define HOFF_VT   (HOFF_KS + 2 * 64 * FQP)   // 26112
#define HOFF_PS   (HOFF_VT + 2 * 128 * FVP)  // 44544
#define HREG_END  (HOFF_PS + 64 * FVP)       // 49152 halves = 98304 B
#define FOFF_SS   (HREG_END / 2)             // float index 49152/2=24576... (bytes/4)
#define FSM_TOTAL (98304 + 64*FSP*4 + 512)   // 116224 bytes

__global__ __launch_bounds__(256, 1) void flash_mma_kernel() {
    extern __shared__ char fsm[];
    __half* Qs  = (__half*)fsm;
    __half* Ksb = Qs + HOFF_KS;
    __half* Vtb = Qs + HOFF_VT;
    __half* Ps  = Qs + HOFF_PS;
    float* Ssc  = (float*)(fsm + 98304);
    float* corr = Ssc + 64 * FSP;
    float* linv = corr + 64;

    const int tid  = threadIdx.x;
    const int warp = tid >> 5;
    const int lid  = tid & 31;
    const int fr = lid >> 2;
    const int fc = lid & 3;
    const int wmS = (warp >> 1) * 16;
    const int wnS = (warp & 1) * 32;
    const int wmO = wmS;
    const int wnO = (warp & 1) * 64;

    const int q0 = blockIdx.x * 64;
    const int h  = blockIdx.y;
    const int b  = blockIdx.z;
    const int hk = h >> 1;

    const __half* qb  = g_qTh + (((size_t)b * NH + h) * Ss + q0) * HD;
    const __half* kb  = g_kTh + ((size_t)b * NKV + hk) * Ss * HD;
    const __half* vtb = g_vTh + ((size_t)b * NKV + hk) * Ss * HD;   // [d][s]

    const int srow = tid >> 2;
    const int ssub = tid & 3;
    float m_old = -1e30f, l_old = 0.f;

    float oa[8][4];
#pragma unroll
    for (int nf = 0; nf < 8; nf++)
#pragma unroll
        for (int j = 0; j < 4; j++) oa[nf][j] = 0.f;

    auto loadQ = [&]() {
#pragma unroll
        for (int i = 0; i < 4; i++) {
            int ch = tid + i * 256;              // 1024 chunks of 8 halves
            int row = ch >> 4, kc = ch & 15;
            cpasync16(s2u(Qs + row * FQP + kc * 8), qb + (size_t)row * HD + kc * 8);
        }
    };
    auto loadK = [&](int j, int s) {
        __half* Kd = Ksb + s * 64 * FQP;
        const __half* src = kb + (size_t)(j * 64) * HD;
#pragma unroll
        for (int i = 0; i < 4; i++) {
            int ch = tid + i * 256;
            int row = ch >> 4, kc = ch & 15;
            cpasync16(s2u(Kd + row * FQP + kc * 8), src + (size_t)row * HD + kc * 8);
        }
    };
    auto loadV = [&](int j, int s) {
        __half* Vd = Vtb + s * 128 * FVP;
#pragma unroll
        for (int i = 0; i < 4; i++) {
            int ch = tid + i * 256;              // 1024 chunks: 128 rows x 8 chunks
            int row = ch >> 3, kc = ch & 7;
            cpasync16(s2u(Vd + row * FVP + kc * 8), vtb + (size_t)row * Ss + j * 64 + kc * 8);
        }
    };

    const int nt = blockIdx.x + 1;
    loadQ(); loadK(0, 0); loadV(0, 0);
    asm volatile("cp.async.commit_group;" ::: "memory");

    for (int j = 0; j < nt; j++) {
        int s = j & 1;
        if (j + 1 < nt) {
            loadK(j + 1, s ^ 1); loadV(j + 1, s ^ 1);
            asm volatile("cp.async.commit_group;" ::: "memory");
            asm volatile("cp.async.wait_group 1;" ::: "memory");
        } else {
            asm volatile("cp.async.wait_group 0;" ::: "memory");
        }
        __syncthreads();

        // ---- S = Q K^T (warp tile 16x32, 8 k16 steps) ----
        const __half* Kf = Ksb + s * 64 * FQP;
        float sa[4][4];
#pragma unroll
        for (int nf = 0; nf < 4; nf++)
#pragma unroll
            for (int t = 0; t < 4; t++) sa[nf][t] = 0.f;
#pragma unroll
        for (int kk = 0; kk < 8; kk++) {
            uint32_t a[4], bfr[4][2];
            const __half* ap = Qs + (wmS + fr) * FQP + kk * 16 + 2 * fc;
            a[0] = ldh2(ap);
            a[1] = ldh2(ap + 8 * FQP);
            a[2] = ldh2(ap + 8);
            a[3] = ldh2(ap + 8 * FQP + 8);
#pragma unroll
            for (int nf = 0; nf < 4; nf++) {
                const __half* bp = Kf + (wnS + nf * 8 + fr) * FQP + kk * 16 + 2 * fc;
                bfr[nf][0] = ldh2(bp);
                bfr[nf][1] = ldh2(bp + 8);
            }
#pragma unroll
            for (int nf = 0; nf < 4; nf++) mma_f16(sa[nf], a, bfr[nf]);
        }
#pragma unroll
        for (int nf = 0; nf < 4; nf++) {
            int col = wnS + nf * 8 + 2 * fc;
            *(float2*)&Ssc[(wmS + fr) * FSP + col]     = make_float2(sa[nf][0], sa[nf][1]);
            *(float2*)&Ssc[(wmS + fr + 8) * FSP + col] = make_float2(sa[nf][2], sa[nf][3]);
        }
        __syncthreads();

        // ---- online softmax (4 threads per row) ----
        {
            float sv[16];
            float mx = -1e30f;
            int qglob = q0 + srow;
#pragma unroll
            for (int i = 0; i < 16; i++) {
                int c = ssub + 4 * i;
                float val = Ssc[srow * FSP + c] * SCALE;
                if (j * 64 + c > qglob) val = -1e9f;
                sv[i] = val;
                mx = fmaxf(mx, val);
            }
            mx = fmaxf(mx, __shfl_xor_sync(0xffffffffu, mx, 1));
            mx = fmaxf(mx, __shfl_xor_sync(0xffffffffu, mx, 2));
            float mnew = fmaxf(m_old, mx);
            float cr = __expf(m_old - mnew);
            float psum = 0.f;
#pragma unroll
            for (int i = 0; i < 16; i++) {
                float p = __expf(sv[i] - mnew);
                psum += p;
                Ps[srow * FVP + ssub + 4 * i] = __float2half_rn(p);
            }
            psum += __shfl_xor_sync(0xffffffffu, psum, 1);
            psum += __shfl_xor_sync(0xffffffffu, psum, 2);
            l_old = l_old * cr + psum;
            m_old = mnew;
            if (ssub == 0) corr[srow] = cr;
        }
        __syncthreads();

        // ---- O = O*corr + P V (warp tile 16x64, 4 k16 steps) ----
        const __half* Vf = Vtb + s * 128 * FVP;
        {
            float cr0 = corr[wmO + fr];
            float cr1 = corr[wmO + fr + 8];
#pragma unroll
            for (int nf = 0; nf < 8; nf++) {
                oa[nf][0] *= cr0; oa[nf][1] *= cr0;
                oa[nf][2] *= cr1; oa[nf][3] *= cr1;
            }
        }
#pragma unroll
        for (int kk = 0; kk < 4; kk++) {
            uint32_t a[4], bfr[8][2];
            const __half* ap = Ps + (wmO + fr) * FVP + kk * 16 + 2 * fc;
            a[0] = ldh2(ap);
            a[1] = ldh2(ap + 8 * FVP);
            a[2] = ldh2(ap + 8);
            a[3] = ldh2(ap + 8 * FVP + 8);
#pragma unroll
            for (int nf = 0; nf < 8; nf++) {
                const __half* bp = Vf + (wnO + nf * 8 + fr) * FVP + kk * 16 + 2 * fc;
                bfr[nf][0] = ldh2(bp);
                bfr[nf][1] = ldh2(bp + 8);
            }
#pragma unroll
            for (int nf = 0; nf < 8; nf++) mma_f16(oa[nf], a, bfr[nf]);
        }
    }

    if (ssub == 0) linv[srow] = 1.0f / l_old;
    __syncthreads();

    // ---- epilogue: normalize, half-round, store to g_attnH ----
    float i0 = linv[wmO + fr];
    float i1 = linv[wmO + fr + 8];
    int row0 = q0 + wmO + fr;
    __half* d0 = g_attnH + ((size_t)(b * Ss + row0) * NH + h) * HD + wnO + 2 * fc;
    __half* d1 = g_attnH + ((size_t)(b * Ss + row0 + 8) * NH + h) * HD + wnO + 2 * fc;
#pragma unroll
    for (int nf = 0; nf < 8; nf++) {
        *(__half2*)(d0 + nf * 8) = __floats2half2_rn(oa[nf][0] * i0, oa[nf][1] * i0);
        *(__half2*)(d1 + nf * 8) = __floats2half2_rn(oa[nf][2] * i1, oa[nf][3] * i1);
    }
}

// ---------------------------------------------------------------------------
extern "C" void kernel_launch(void* const* d_in, const int* in_sizes, int n_in,
                              void* d_out, int out_size) {
    const float* x    = (const float*)d_in[0];
    const float* cosb = (const float*)d_in[1];
    const float* sinb = (const float*)d_in[2];
    const float* Wq = (const float*)d_in[4];
    const float* Wk = (const float*)d_in[5];
    const float* Wv = (const float*)d_in[6];
    const float* Wo = (const float*)d_in[7];
    const float* qw = (const float*)d_in[8];
    const float* kw = (const float*)d_in[9];
    float* out = (float*)d_out;

    float *qbuf, *kbuf, *vbuf;
    __half *xH, *wqH, *wkH, *wvH, *woH, *attnH;
    cudaGetSymbolAddress((void**)&qbuf, g_qbuf);
    cudaGetSymbolAddress((void**)&kbuf, g_kbuf);
    cudaGetSymbolAddress((void**)&vbuf, g_vbuf);
    cudaGetSymbolAddress((void**)&xH,  g_xH);
    cudaGetSymbolAddress((void**)&wqH, g_wqH);
    cudaGetSymbolAddress((void**)&wkH, g_wkH);
    cudaGetSymbolAddress((void**)&wvH, g_wvH);
    cudaGetSymbolAddress((void**)&woH, g_woH);
    cudaGetSymbolAddress((void**)&attnH, g_attnH);

    cudaFuncSetAttribute(gemm_f16, cudaFuncAttributeMaxDynamicSharedMemorySize, GSM_TOTAL);
    cudaFuncSetAttribute(flash_mma_kernel, cudaFuncAttributeMaxDynamicSharedMemorySize, FSM_TOTAL);

    // fp16 packs of GEMM operands
    cvt_f2h_kernel<<<(MROWS * HID) / 2048, 256>>>(x,  xH,  MROWS * HID);
    cvt_f2h_kernel<<<(QDIM * HID) / 2048, 256>>>(Wq, wqH, QDIM * HID);
    cvt_f2h_kernel<<<(KDIM * HID) / 2048, 256>>>(Wk, wkH, KDIM * HID);
    cvt_f2h_kernel<<<(KDIM * HID) / 2048, 256>>>(Wv, wvH, KDIM * HID);
    cvt_f2h_kernel<<<(HID * QDIM) / 2048, 256>>>(Wo, woH, HID * QDIM);

    // QKV projections (f16 mma)
    gemm_f16<<<dim3(QDIM / 128, MROWS / 128), 256, GSM_TOTAL>>>(xH, wqH, qbuf, MROWS, QDIM, HID);
    gemm_f16<<<dim3(KDIM / 128, MROWS / 128), 256, GSM_TOTAL>>>(xH, wkH, kbuf, MROWS, KDIM, HID);
    gemm_f16<<<dim3(KDIM / 128, MROWS / 128), 256, GSM_TOTAL>>>(xH, wvH, vbuf, MROWS, KDIM, HID);

    // RMSNorm + RoPE + transpose (half outputs; V d-major)
    normrope_kernel<<<(MROWS * 32) / 8, 256>>>(cosb, sinb, qw, kw);

    // fp16 tensorized causal flash attention
    flash_mma_kernel<<<dim3(Ss / 64, NH, Bb), 256, FSM_TOTAL>>>();

    // Output projection (f16 mma, fp32 out)
    gemm_f16<<<dim3(HID / 128, MROWS / 128), 256, GSM_TOTAL>>>(attnH, woH, out, MROWS, HID, QDIM);
}

// round 6
// speedup vs baseline: 8.6641x; 1.1952x over previous
#include <cuda_runtime.h>
#include <cuda_fp16.h>
#include <cstdint>

// Problem constants
#define Bb   2
#define Ss   2048
#define HID  1024
#define NH   16
#define NKV  8
#define HD   128
#define MROWS (Bb*Ss)          // 4096
#define QDIM (NH*HD)           // 2048
#define KDIM (NKV*HD)          // 1024
#define NQKV (QDIM + 2*KDIM)   // 4096 combined
#define SCALE 0.08838834764831845f

// ---------------------------------------------------------------------------
// Scratch (static device memory; no allocation APIs)
// ---------------------------------------------------------------------------
__device__ __half g_qTh[(size_t)Bb * NH * Ss * HD];    // [b][h][s][d]
__device__ __half g_kTh[(size_t)Bb * NKV * Ss * HD];   // [b][hk][s][d]
__device__ __half g_vTh[(size_t)Bb * NKV * Ss * HD];   // [b][hk][d][s] transposed
__device__ __half g_attnH[(size_t)MROWS * QDIM];       // flash output (half)
__device__ __half g_xH[(size_t)MROWS * HID];
__device__ __half g_wqkvH[(size_t)NQKV * HID];         // [Wq;Wk;Wv] rows
__device__ __half g_woH[(size_t)HID * QDIM];

__device__ __forceinline__ uint32_t s2u(const void* p) {
    uint32_t a;
    asm("{ .reg .u64 t; cvta.to.shared.u64 t, %1; cvt.u32.u64 %0, t; }" : "=r"(a) : "l"(p));
    return a;
}
__device__ __forceinline__ void cpasync16(uint32_t dst, const void* src) {
    asm volatile("cp.async.cg.shared.global [%0], [%1], 16;" :: "r"(dst), "l"(src));
}
__device__ __forceinline__ void mma_f16(float* c, const uint32_t* a, const uint32_t* b) {
    asm volatile(
        "mma.sync.aligned.m16n8k16.row.col.f32.f16.f16.f32 "
        "{%0,%1,%2,%3}, {%4,%5,%6,%7}, {%8,%9}, {%0,%1,%2,%3};"
        : "+f"(c[0]), "+f"(c[1]), "+f"(c[2]), "+f"(c[3])
        : "r"(a[0]), "r"(a[1]), "r"(a[2]), "r"(a[3]), "r"(b[0]), "r"(b[1]));
}
__device__ __forceinline__ uint32_t ldh2(const __half* p) { return *(const uint32_t*)p; }

// ---------------------------------------------------------------------------
// float -> half packs
// ---------------------------------------------------------------------------
__global__ __launch_bounds__(256) void cvt_f2h_kernel(const float* __restrict__ src,
                                                      __half* __restrict__ dst, int n) {
    int i = (blockIdx.x * 256 + threadIdx.x) * 8;
    if (i < n) {
        float4 v0 = *(const float4*)(src + i);
        float4 v1 = *(const float4*)(src + i + 4);
        __half2* d = (__half2*)(dst + i);
        d[0] = __floats2half2_rn(v0.x, v0.y);
        d[1] = __floats2half2_rn(v0.z, v0.w);
        d[2] = __floats2half2_rn(v1.x, v1.y);
        d[3] = __floats2half2_rn(v1.z, v1.w);
    }
}

__global__ __launch_bounds__(256) void cvt_qkv_kernel(const float* __restrict__ wq,
                                                      const float* __restrict__ wk,
                                                      const float* __restrict__ wv,
                                                      __half* __restrict__ dst) {
    int i = (blockIdx.x * 256 + threadIdx.x) * 8;   // 4M elements total
    const float* src;
    int off;
    if (i < QDIM * HID)            { src = wq; off = i; }
    else if (i < (QDIM + KDIM) * HID) { src = wk; off = i - QDIM * HID; }
    else                           { src = wv; off = i - (QDIM + KDIM) * HID; }
    float4 v0 = *(const float4*)(src + off);
    float4 v1 = *(const float4*)(src + off + 4);
    __half2* d = (__half2*)(dst + i);
    d[0] = __floats2half2_rn(v0.x, v0.y);
    d[1] = __floats2half2_rn(v0.z, v0.w);
    d[2] = __floats2half2_rn(v1.x, v1.y);
    d[3] = __floats2half2_rn(v1.z, v1.w);
}

// ---------------------------------------------------------------------------
// Shared GEMM mainloop machinery: BM=128, BN=128, BK=64, 256 threads,
// 8 warps (4x2), warp tile 32x64. Double-buffered cp.async.
// smem pitch 72 halves -> conflict-free fragment loads.
// ---------------------------------------------------------------------------
#define GPADH 72
#define TILE_H (128 * GPADH)                // 9216 halves per operand tile
#define GSM_TOTAL (4 * TILE_H * 2)          // 73728 B: [A0][A1][B0][B1]

// Runs the full K loop, leaves results in acc[2][8][4].
// Template-free macro-style via inline function with pointers.
__device__ __forceinline__ void gemm_mainloop(const __half* __restrict__ A,
                                              const __half* __restrict__ B,
                                              __half* As, __half* Bs,
                                              int r0, int c0, int K,
                                              int tid, int wm, int wn, int fr, int fc,
                                              float acc[2][8][4]) {
#pragma unroll
    for (int mi = 0; mi < 2; mi++)
#pragma unroll
        for (int ni = 0; ni < 8; ni++)
#pragma unroll
            for (int j = 0; j < 4; j++) acc[mi][ni][j] = 0.f;

    const int T = K >> 6;

    auto load_tile = [&](int t, int s) {
        __half* Ad = As + s * TILE_H;
        __half* Bd = Bs + s * TILE_H;
        const __half* Ap = A + (size_t)r0 * K + t * 64;
        const __half* Bp = B + (size_t)c0 * K + t * 64;
#pragma unroll
        for (int i = 0; i < 4; i++) {
            int ch = tid + i * 256;             // 1024 chunks of 8 halves
            int row = ch >> 3, kc = ch & 7;
            cpasync16(s2u(Ad + row * GPADH + kc * 8), Ap + (size_t)row * K + kc * 8);
            cpasync16(s2u(Bd + row * GPADH + kc * 8), Bp + (size_t)row * K + kc * 8);
        }
        asm volatile("cp.async.commit_group;" ::: "memory");
    };

    load_tile(0, 0);

    for (int t = 0; t < T; t++) {
        int s = t & 1;
        if (t + 1 < T) load_tile(t + 1, s ^ 1);
        if (t + 1 < T) asm volatile("cp.async.wait_group 1;" ::: "memory");
        else           asm volatile("cp.async.wait_group 0;" ::: "memory");
        __syncthreads();

        const __half* Af = As + s * TILE_H;
        const __half* Bf = Bs + s * TILE_H;
#pragma unroll
        for (int kk = 0; kk < 4; kk++) {
            uint32_t a[2][4], b[8][2];
#pragma unroll
            for (int mi = 0; mi < 2; mi++) {
                const __half* p = Af + (wm + mi * 16 + fr) * GPADH + kk * 16 + 2 * fc;
                a[mi][0] = ldh2(p);
                a[mi][1] = ldh2(p + 8 * GPADH);
                a[mi][2] = ldh2(p + 8);
                a[mi][3] = ldh2(p + 8 * GPADH + 8);
            }
#pragma unroll
            for (int ni = 0; ni < 8; ni++) {
                const __half* p = Bf + (wn + ni * 8 + fr) * GPADH + kk * 16 + 2 * fc;
                b[ni][0] = ldh2(p);
                b[ni][1] = ldh2(p + 8);
            }
#pragma unroll
            for (int mi = 0; mi < 2; mi++)
#pragma unroll
                for (int ni = 0; ni < 8; ni++)
                    mma_f16(acc[mi][ni], a[mi], b[ni]);
        }
        __syncthreads();
    }
}

// ---------------------------------------------------------------------------
// Fused QKV GEMM + RMSNorm + RoPE + transpose.
// C tile (128 tokens x 128 dims) == one head vector per column tile:
//   blockIdx.x in [0,16): Q head; [16,24): K head; [24,32): V head.
// Epilogue stages acc to smem (float, pitch 132), then per-row norm/rope
// with half stores into g_qTh/g_kTh (token-major) or g_vTh (d-major).
// ---------------------------------------------------------------------------
__global__ __launch_bounds__(256, 2) void gemm_qkv_fused(const __half* __restrict__ A,
                                                         const __half* __restrict__ B,
                                                         const float* __restrict__ cosb,
                                                         const float* __restrict__ sinb,
                                                         const float* __restrict__ qw,
                                                         const float* __restrict__ kw) {
    extern __shared__ __half hsm[];
    __half* As = hsm;
    __half* Bs = hsm + 2 * TILE_H;

    const int tid  = threadIdx.x;
    const int warp = tid >> 5;
    const int lane = tid & 31;
    const int wm = (warp >> 1) * 32;
    const int wn = (warp & 1) * 64;
    const int fr = lane >> 2;
    const int fc = lane & 3;

    const int head = blockIdx.x;
    const int r0 = blockIdx.y * 128;

    float acc[2][8][4];
    gemm_mainloop(A, B, As, Bs, r0, head * 128, HID, tid, wm, wn, fr, fc, acc);

    // Stage to smem as float, pitch 132
    float* S = (float*)hsm;
#pragma unroll
    for (int mi = 0; mi < 2; mi++) {
        int row = wm + mi * 16 + fr;
#pragma unroll
        for (int ni = 0; ni < 8; ni++) {
            int col = wn + ni * 8 + 2 * fc;
            *(float2*)&S[row * 132 + col]       = make_float2(acc[mi][ni][0], acc[mi][ni][1]);
            *(float2*)&S[(row + 8) * 132 + col] = make_float2(acc[mi][ni][2], acc[mi][ni][3]);
        }
    }
    __syncthreads();

    if (head < 24) {
        // Q or K: RMSNorm + RoPE, token-major half store
        const float* w = (head < 16) ? qw : kw;
        __half* base = (head < 16)
            ? g_qTh + (size_t)head * Ss * HD            // offset by b later
            : g_kTh + (size_t)(head - 16) * Ss * HD;
        int nheads = (head < 16) ? NH : NKV;
#pragma unroll 1
        for (int it = 0; it < 16; it++) {
            int row = it * 8 + warp;
            int glob = r0 + row;
            int b = glob >> 11, s = glob & 2047;
            float x0 = S[row * 132 + lane];
            float x1 = S[row * 132 + lane + 32];
            float x2 = S[row * 132 + lane + 64];
            float x3 = S[row * 132 + lane + 96];
            float ssq = x0 * x0 + x1 * x1 + x2 * x2 + x3 * x3;
#pragma unroll
            for (int o = 16; o; o >>= 1) ssq += __shfl_xor_sync(0xffffffffu, ssq, o);
            float inv = rsqrtf(ssq * (1.0f / 128.0f) + 1e-6f);
            x0 = x0 * inv * w[lane];
            x1 = x1 * inv * w[lane + 32];
            x2 = x2 * inv * w[lane + 64];
            x3 = x3 * inv * w[lane + 96];
            const float* cp = cosb + (size_t)glob * HD;
            const float* sp = sinb + (size_t)glob * HD;
            float c0 = cp[lane], c1 = cp[lane + 32], c2 = cp[lane + 64], c3 = cp[lane + 96];
            float s0 = sp[lane], s1 = sp[lane + 32], s2 = sp[lane + 64], s3 = sp[lane + 96];
            __half* dst = base + ((size_t)b * nheads * Ss + s) * HD;
            dst[lane]      = __float2half_rn(x0 * c0 - x2 * s0);
            dst[lane + 32] = __float2half_rn(x1 * c1 - x3 * s1);
            dst[lane + 64] = __float2half_rn(x2 * c2 + x0 * s2);
            dst[lane + 96] = __float2half_rn(x3 * c3 + x1 * s3);
        }
    } else {
        // V: transpose to d-major half
        int h = head - 24;
        int b = r0 >> 11, s0 = r0 & 2047;
        __half* dst = g_vTh + ((size_t)b * NKV + h) * Ss * HD;
#pragma unroll 1
        for (int it = 0; it < 16; it++) {
            int d = it * 8 + warp;
#pragma unroll
            for (int j = 0; j < 4; j++) {
                float v = S[(lane + 32 * j) * 132 + d];
                dst[(size_t)d * Ss + s0 + lane + 32 * j] = __float2half_rn(v);
            }
        }
    }
}

// ---------------------------------------------------------------------------
// O-projection GEMM: C[M][N](f32) = A[M][K] * B[N][K]^T
// ---------------------------------------------------------------------------
__global__ __launch_bounds__(256, 2) void gemm_f16(const __half* __restrict__ A,
                                                   const __half* __restrict__ B,
                                                   float* __restrict__ C,
                                                   int M, int N, int K) {
    extern __shared__ __half hsm[];
    __half* As = hsm;
    __half* Bs = hsm + 2 * TILE_H;

    const int tid  = threadIdx.x;
    const int warp = tid >> 5;
    const int lid  = tid & 31;
    const int wm = (warp >> 1) * 32;
    const int wn = (warp & 1) * 64;
    const int fr = lid >> 2;
    const int fc = lid & 3;

    const int r0 = blockIdx.y * 128;
    const int c0 = blockIdx.x * 128;

    float acc[2][8][4];
    gemm_mainloop(A, B, As, Bs, r0, c0, K, tid, wm, wn, fr, fc, acc);

#pragma unroll
    for (int mi = 0; mi < 2; mi++) {
        int row = r0 + wm + mi * 16 + fr;
        float* cp0 = C + (size_t)row * N + c0 + wn + fc * 2;
        float* cp1 = C + (size_t)(row + 8) * N + c0 + wn + fc * 2;
#pragma unroll
        for (int ni = 0; ni < 8; ni++) {
            *(float2*)(cp0 + ni * 8) = make_float2(acc[mi][ni][0], acc[mi][ni][1]);
            *(float2*)(cp1 + ni * 8) = make_float2(acc[mi][ni][2], acc[mi][ni][3]);
        }
    }
}

// ---------------------------------------------------------------------------
// fp16 tensorized flash attention, causal, GQA (unchanged from R5).
// ---------------------------------------------------------------------------
#define FQP 136
#define FVP 72
#define FSP 68
#define HOFF_KS   (64 * FQP)
#define HOFF_VT   (HOFF_KS + 2 * 64 * FQP)
#define HOFF_PS   (HOFF_VT + 2 * 128 * FVP)
#define FSM_TOTAL (98304 + 64*FSP*4 + 512)

__global__ __launch_bounds__(256, 1) void flash_mma_kernel() {
    extern __shared__ char fsm[];
    __half* Qs  = (__half*)fsm;
    __half* Ksb = Qs + HOFF_KS;
    __half* Vtb = Qs + HOFF_VT;
    __half* Ps  = Qs + HOFF_PS;
    float* Ssc  = (float*)(fsm + 98304);
    float* corr = Ssc + 64 * FSP;
    float* linv = corr + 64;

    const int tid  = threadIdx.x;
    const int warp = tid >> 5;
    const int lid  = tid & 31;
    const int fr = lid >> 2;
    const int fc = lid & 3;
    const int wmS = (warp >> 1) * 16;
    const int wnS = (warp & 1) * 32;
    const int wmO = wmS;
    const int wnO = (warp & 1) * 64;

    const int q0 = blockIdx.x * 64;
    const int h  = blockIdx.y;
    const int b  = blockIdx.z;
    const int hk = h >> 1;

    const __half* qb  = g_qTh + (((size_t)b * NH + h) * Ss + q0) * HD;
    const __half* kb  = g_kTh + ((size_t)b * NKV + hk) * Ss * HD;
    const __half* vtb = g_vTh + ((size_t)b * NKV + hk) * Ss * HD;

    const int srow = tid >> 2;
    const int ssub = tid & 3;
    float m_old = -1e30f, l_old = 0.f;

    float oa[8][4];
#pragma unroll
    for (int nf = 0; nf < 8; nf++)
#pragma unroll
        for (int j = 0; j < 4; j++) oa[nf][j] = 0.f;

    auto loadQ = [&]() {
#pragma unroll
        for (int i = 0; i < 4; i++) {
            int ch = tid + i * 256;
            int row = ch >> 4, kc = ch & 15;
            cpasync16(s2u(Qs + row * FQP + kc * 8), qb + (size_t)row * HD + kc * 8);
        }
    };
    auto loadK = [&](int j, int s) {
        __half* Kd = Ksb + s * 64 * FQP;
        const __half* src = kb + (size_t)(j * 64) * HD;
#pragma unroll
        for (int i = 0; i < 4; i++) {
            int ch = tid + i * 256;
            int row = ch >> 4, kc = ch & 15;
            cpasync16(s2u(Kd + row * FQP + kc * 8), src + (size_t)row * HD + kc * 8);
        }
    };
    auto loadV = [&](int j, int s) {
        __half* Vd = Vtb + s * 128 * FVP;
#pragma unroll
        for (int i = 0; i < 4; i++) {
            int ch = tid + i * 256;
            int row = ch >> 3, kc = ch & 7;
            cpasync16(s2u(Vd + row * FVP + kc * 8), vtb + (size_t)row * Ss + j * 64 + kc * 8);
        }
    };

    const int nt = blockIdx.x + 1;
    loadQ(); loadK(0, 0); loadV(0, 0);
    asm volatile("cp.async.commit_group;" ::: "memory");

    for (int j = 0; j < nt; j++) {
        int s = j & 1;
        if (j + 1 < nt) {
            loadK(j + 1, s ^ 1); loadV(j + 1, s ^ 1);
            asm volatile("cp.async.commit_group;" ::: "memory");
            asm volatile("cp.async.wait_group 1;" ::: "memory");
        } else {
            asm volatile("cp.async.wait_group 0;" ::: "memory");
        }
        __syncthreads();

        const __half* Kf = Ksb + s * 64 * FQP;
        float sa[4][4];
#pragma unroll
        for (int nf = 0; nf < 4; nf++)
#pragma unroll
            for (int t = 0; t < 4; t++) sa[nf][t] = 0.f;
#pragma unroll
        for (int kk = 0; kk < 8; kk++) {
            uint32_t a[4], bfr[4][2];
            const __half* ap = Qs + (wmS + fr) * FQP + kk * 16 + 2 * fc;
            a[0] = ldh2(ap);
            a[1] = ldh2(ap + 8 * FQP);
            a[2] = ldh2(ap + 8);
            a[3] = ldh2(ap + 8 * FQP + 8);
#pragma unroll
            for (int nf = 0; nf < 4; nf++) {
                const __half* bp = Kf + (wnS + nf * 8 + fr) * FQP + kk * 16 + 2 * fc;
                bfr[nf][0] = ldh2(bp);
                bfr[nf][1] = ldh2(bp + 8);
            }
#pragma unroll
            for (int nf = 0; nf < 4; nf++) mma_f16(sa[nf], a, bfr[nf]);
        }
#pragma unroll
        for (int nf = 0; nf < 4; nf++) {
            int col = wnS + nf * 8 + 2 * fc;
            *(float2*)&Ssc[(wmS + fr) * FSP + col]     = make_float2(sa[nf][0], sa[nf][1]);
            *(float2*)&Ssc[(wmS + fr + 8) * FSP + col] = make_float2(sa[nf][2], sa[nf][3]);
        }
        __syncthreads();

        {
            float sv[16];
            float mx = -1e30f;
            int qglob = q0 + srow;
#pragma unroll
            for (int i = 0; i < 16; i++) {
                int c = ssub + 4 * i;
                float val = Ssc[srow * FSP + c] * SCALE;
                if (j * 64 + c > qglob) val = -1e9f;
                sv[i] = val;
                mx = fmaxf(mx, val);
            }
            mx = fmaxf(mx, __shfl_xor_sync(0xffffffffu, mx, 1));
            mx = fmaxf(mx, __shfl_xor_sync(0xffffffffu, mx, 2));
            float mnew = fmaxf(m_old, mx);
            float cr = __expf(m_old - mnew);
            float psum = 0.f;
#pragma unroll
            for (int i = 0; i < 16; i++) {
                float p = __expf(sv[i] - mnew);
                psum += p;
                Ps[srow * FVP + ssub + 4 * i] = __float2half_rn(p);
            }
            psum += __shfl_xor_sync(0xffffffffu, psum, 1);
            psum += __shfl_xor_sync(0xffffffffu, psum, 2);
            l_old = l_old * cr + psum;
            m_old = mnew;
            if (ssub == 0) corr[srow] = cr;
        }
        __syncthreads();

        const __half* Vf = Vtb + s * 128 * FVP;
        {
            float cr0 = corr[wmO + fr];
            float cr1 = corr[wmO + fr + 8];
#pragma unroll
            for (int nf = 0; nf < 8; nf++) {
                oa[nf][0] *= cr0; oa[nf][1] *= cr0;
                oa[nf][2] *= cr1; oa[nf][3] *= cr1;
            }
        }
#pragma unroll
        for (int kk = 0; kk < 4; kk++) {
            uint32_t a[4], bfr[8][2];
            const __half* ap = Ps + (wmO + fr) * FVP + kk * 16 + 2 * fc;
            a[0] = ldh2(ap);
            a[1] = ldh2(ap + 8 * FVP);
            a[2] = ldh2(ap + 8);
            a[3] = ldh2(ap + 8 * FVP + 8);
#pragma unroll
            for (int nf = 0; nf < 8; nf++) {
                const __half* bp = Vf + (wnO + nf * 8 + fr) * FVP + kk * 16 + 2 * fc;
                bfr[nf][0] = ldh2(bp);
                bfr[nf][1] = ldh2(bp + 8);
            }
#pragma unroll
            for (int nf = 0; nf < 8; nf++) mma_f16(oa[nf], a, bfr[nf]);
        }
    }

    if (ssub == 0) linv[srow] = 1.0f / l_old;
    __syncthreads();

    float i0 = linv[wmO + fr];
    float i1 = linv[wmO + fr + 8];
    int row0 = q0 + wmO + fr;
    __half* d0 = g_attnH + ((size_t)(b * Ss + row0) * NH + h) * HD + wnO + 2 * fc;
    __half* d1 = g_attnH + ((size_t)(b * Ss + row0 + 8) * NH + h) * HD + wnO + 2 * fc;
#pragma unroll
    for (int nf = 0; nf < 8; nf++) {
        *(__half2*)(d0 + nf * 8) = __floats2half2_rn(oa[nf][0] * i0, oa[nf][1] * i0);
        *(__half2*)(d1 + nf * 8) = __floats2half2_rn(oa[nf][2] * i1, oa[nf][3] * i1);
    }
}

// ---------------------------------------------------------------------------
extern "C" void kernel_launch(void* const* d_in, const int* in_sizes, int n_in,
                              void* d_out, int out_size) {
    const float* x    = (const float*)d_in[0];
    const float* cosb = (const float*)d_in[1];
    const float* sinb = (const float*)d_in[2];
    const float* Wq = (const float*)d_in[4];
    const float* Wk = (const float*)d_in[5];
    const float* Wv = (const float*)d_in[6];
    const float* Wo = (const float*)d_in[7];
    const float* qw = (const float*)d_in[8];
    const float* kw = (const float*)d_in[9];
    float* out = (float*)d_out;

    __half *xH, *wqkvH, *woH, *attnH;
    cudaGetSymbolAddress((void**)&xH,    g_xH);
    cudaGetSymbolAddress((void**)&wqkvH, g_wqkvH);
    cudaGetSymbolAddress((void**)&woH,   g_woH);
    cudaGetSymbolAddress((void**)&attnH, g_attnH);

    cudaFuncSetAttribute(gemm_qkv_fused, cudaFuncAttributeMaxDynamicSharedMemorySize, GSM_TOTAL);
    cudaFuncSetAttribute(gemm_f16, cudaFuncAttributeMaxDynamicSharedMemorySize, GSM_TOTAL);
    cudaFuncSetAttribute(flash_mma_kernel, cudaFuncAttributeMaxDynamicSharedMemorySize, FSM_TOTAL);

    // fp16 packs
    cvt_f2h_kernel<<<(MROWS * HID) / 2048, 256>>>(x, xH, MROWS * HID);
    cvt_qkv_kernel<<<(NQKV * HID) / 2048, 256>>>(Wq, Wk, Wv, wqkvH);
    cvt_f2h_kernel<<<(HID * QDIM) / 2048, 256>>>(Wo, woH, HID * QDIM);

    // Fused QKV projection + RMSNorm + RoPE + transpose
    gemm_qkv_fused<<<dim3(NQKV / 128, MROWS / 128), 256, GSM_TOTAL>>>(
        xH, wqkvH, cosb, sinb, qw, kw);

    // fp16 tensorized causal flash attention
    flash_mma_kernel<<<dim3(Ss / 64, NH, Bb), 256, FSM_TOTAL>>>();

    // Output projection
    gemm_f16<<<dim3(HID / 128, MROWS / 128), 256, GSM_TOTAL>>>(attnH, woH, out, MROWS, HID, QDIM);
}

// round 7
// speedup vs baseline: 8.9587x; 1.0340x over previous
#include <cuda_runtime.h>
#include <cuda_fp16.h>
#include <cstdint>

// Problem constants
#define Bb   2
#define Ss   2048
#define HID  1024
#define NH   16
#define NKV  8
#define HD   128
#define MROWS (Bb*Ss)          // 4096
#define QDIM (NH*HD)           // 2048
#define KDIM (NKV*HD)          // 1024
#define NQKV (QDIM + 2*KDIM)   // 4096 combined
#define SCALE 0.08838834764831845f

// ---------------------------------------------------------------------------
// Scratch (static device memory; no allocation APIs)
// ---------------------------------------------------------------------------
__device__ __half g_qTh[(size_t)Bb * NH * Ss * HD];    // [b][h][s][d]
__device__ __half g_kTh[(size_t)Bb * NKV * Ss * HD];   // [b][hk][s][d]
__device__ __half g_vTh[(size_t)Bb * NKV * Ss * HD];   // [b][hk][d][s] transposed
__device__ __half g_attnH[(size_t)MROWS * QDIM];       // flash output (half)
__device__ __half g_xH[(size_t)MROWS * HID];
__device__ __half g_wqkvH[(size_t)NQKV * HID];         // [Wq;Wk;Wv] rows
__device__ __half g_woH[(size_t)HID * QDIM];

__device__ __forceinline__ uint32_t s2u(const void* p) {
    uint32_t a;
    asm("{ .reg .u64 t; cvta.to.shared.u64 t, %1; cvt.u32.u64 %0, t; }" : "=r"(a) : "l"(p));
    return a;
}
__device__ __forceinline__ void cpasync16(uint32_t dst, const void* src) {
    asm volatile("cp.async.cg.shared.global [%0], [%1], 16;" :: "r"(dst), "l"(src));
}
__device__ __forceinline__ void mma_f16(float* c, const uint32_t* a, const uint32_t* b) {
    asm volatile(
        "mma.sync.aligned.m16n8k16.row.col.f32.f16.f16.f32 "
        "{%0,%1,%2,%3}, {%4,%5,%6,%7}, {%8,%9}, {%0,%1,%2,%3};"
        : "+f"(c[0]), "+f"(c[1]), "+f"(c[2]), "+f"(c[3])
        : "r"(a[0]), "r"(a[1]), "r"(a[2]), "r"(a[3]), "r"(b[0]), "r"(b[1]));
}
__device__ __forceinline__ void ldmx4(uint32_t* r, uint32_t addr) {
    asm volatile("ldmatrix.sync.aligned.m8n8.x4.shared.b16 {%0,%1,%2,%3}, [%4];"
        : "=r"(r[0]), "=r"(r[1]), "=r"(r[2]), "=r"(r[3]) : "r"(addr));
}

// ---------------------------------------------------------------------------
// float -> half packs
// ---------------------------------------------------------------------------
__global__ __launch_bounds__(256) void cvt_f2h_kernel(const float* __restrict__ src,
                                                      __half* __restrict__ dst, int n) {
    int i = (blockIdx.x * 256 + threadIdx.x) * 8;
    if (i < n) {
        float4 v0 = *(const float4*)(src + i);
        float4 v1 = *(const float4*)(src + i + 4);
        __half2* d = (__half2*)(dst + i);
        d[0] = __floats2half2_rn(v0.x, v0.y);
        d[1] = __floats2half2_rn(v0.z, v0.w);
        d[2] = __floats2half2_rn(v1.x, v1.y);
        d[3] = __floats2half2_rn(v1.z, v1.w);
    }
}

__global__ __launch_bounds__(256) void cvt_qkv_kernel(const float* __restrict__ wq,
                                                      const float* __restrict__ wk,
                                                      const float* __restrict__ wv,
                                                      __half* __restrict__ dst) {
    int i = (blockIdx.x * 256 + threadIdx.x) * 8;
    const float* src;
    int off;
    if (i < QDIM * HID)               { src = wq; off = i; }
    else if (i < (QDIM + KDIM) * HID) { src = wk; off = i - QDIM * HID; }
    else                              { src = wv; off = i - (QDIM + KDIM) * HID; }
    float4 v0 = *(const float4*)(src + off);
    float4 v1 = *(const float4*)(src + off + 4);
    __half2* d = (__half2*)(dst + i);
    d[0] = __floats2half2_rn(v0.x, v0.y);
    d[1] = __floats2half2_rn(v0.z, v0.w);
    d[2] = __floats2half2_rn(v1.x, v1.y);
    d[3] = __floats2half2_rn(v1.z, v1.w);
}

// ---------------------------------------------------------------------------
// Shared GEMM mainloop: BM=128, BN=128, BK=64, 256 threads (8 warps 4x2),
// warp tile 32x64. Double-buffered cp.async, ldmatrix fragment loads.
// smem pitch 72 halves -> ldmatrix reads touch all 32 banks once.
// ---------------------------------------------------------------------------
#define GPADH 72
#define TILE_H (128 * GPADH)                // 9216 halves per operand tile
#define GSM_TOTAL (4 * TILE_H * 2)          // 73728 B: [A0][A1][B0][B1]

__device__ __forceinline__ void gemm_mainloop(const __half* __restrict__ A,
                                              const __half* __restrict__ B,
                                              __half* As, __half* Bs,
                                              int r0, int c0, int K,
                                              int tid, int wm, int wn,
                                              float acc[2][8][4]) {
#pragma unroll
    for (int mi = 0; mi < 2; mi++)
#pragma unroll
        for (int ni = 0; ni < 8; ni++)
#pragma unroll
            for (int j = 0; j < 4; j++) acc[mi][ni][j] = 0.f;

    const int lane = tid & 31;
    const int l7  = lane & 7;
    const int l8  = (lane >> 3) & 1;
    const int l16 = lane >> 4;

    // ldmatrix lane base offsets (bytes)
    const uint32_t aoff = (uint32_t)(((wm + l7 + l8 * 8) * GPADH + l16 * 8) * 2);
    const uint32_t boff = (uint32_t)(((wn + l7 + l16 * 8) * GPADH + l8 * 8) * 2);
    const uint32_t asu = s2u(As);
    const uint32_t bsu = s2u(Bs);

    const int T = K >> 6;

    auto load_tile = [&](int t, int s) {
        __half* Ad = As + s * TILE_H;
        __half* Bd = Bs + s * TILE_H;
        const __half* Ap = A + (size_t)r0 * K + t * 64;
        const __half* Bp = B + (size_t)c0 * K + t * 64;
#pragma unroll
        for (int i = 0; i < 4; i++) {
            int ch = tid + i * 256;
            int row = ch >> 3, kc = ch & 7;
            cpasync16(s2u(Ad + row * GPADH + kc * 8), Ap + (size_t)row * K + kc * 8);
            cpasync16(s2u(Bd + row * GPADH + kc * 8), Bp + (size_t)row * K + kc * 8);
        }
        asm volatile("cp.async.commit_group;" ::: "memory");
    };

    load_tile(0, 0);

    for (int t = 0; t < T; t++) {
        int s = t & 1;
        if (t + 1 < T) load_tile(t + 1, s ^ 1);
        if (t + 1 < T) asm volatile("cp.async.wait_group 1;" ::: "memory");
        else           asm volatile("cp.async.wait_group 0;" ::: "memory");
        __syncthreads();

        const uint32_t af = asu + (uint32_t)(s * TILE_H * 2) + aoff;
        const uint32_t bf = bsu + (uint32_t)(s * TILE_H * 2) + boff;
#pragma unroll
        for (int kk = 0; kk < 4; kk++) {
            uint32_t a[2][4], b[8][2];
            ldmx4(a[0], af + kk * 32);
            ldmx4(a[1], af + 16 * GPADH * 2 + kk * 32);
#pragma unroll
            for (int j = 0; j < 4; j++) {
                uint32_t tmp[4];
                ldmx4(tmp, bf + j * 16 * GPADH * 2 + kk * 32);
                b[2 * j][0]     = tmp[0];
                b[2 * j][1]     = tmp[1];
                b[2 * j + 1][0] = tmp[2];
                b[2 * j + 1][1] = tmp[3];
            }
#pragma unroll
            for (int mi = 0; mi < 2; mi++)
#pragma unroll
                for (int ni = 0; ni < 8; ni++)
                    mma_f16(acc[mi][ni], a[mi], b[ni]);
        }
        __syncthreads();
    }
}

// ---------------------------------------------------------------------------
// Fused QKV GEMM + RMSNorm + RoPE + transpose.
// blockIdx.x in [0,16): Q head; [16,24): K head; [24,32): V head.
// ---------------------------------------------------------------------------
__global__ __launch_bounds__(256, 2) void gemm_qkv_fused(const __half* __restrict__ A,
                                                         const __half* __restrict__ B,
                                                         const float* __restrict__ cosb,
                                                         const float* __restrict__ sinb,
                                                         const float* __restrict__ qw,
                                                         const float* __restrict__ kw) {
    extern __shared__ __half hsm[];
    __half* As = hsm;
    __half* Bs = hsm + 2 * TILE_H;

    const int tid  = threadIdx.x;
    const int warp = tid >> 5;
    const int lane = tid & 31;
    const int wm = (warp >> 1) * 32;
    const int wn = (warp & 1) * 64;
    const int fr = lane >> 2;
    const int fc = lane & 3;

    const int head = blockIdx.x;
    const int r0 = blockIdx.y * 128;

    float acc[2][8][4];
    gemm_mainloop(A, B, As, Bs, r0, head * 128, HID, tid, wm, wn, acc);

    // Stage to smem as float, pitch 132
    float* S = (float*)hsm;
#pragma unroll
    for (int mi = 0; mi < 2; mi++) {
        int row = wm + mi * 16 + fr;
#pragma unroll
        for (int ni = 0; ni < 8; ni++) {
            int col = wn + ni * 8 + 2 * fc;
            *(float2*)&S[row * 132 + col]       = make_float2(acc[mi][ni][0], acc[mi][ni][1]);
            *(float2*)&S[(row + 8) * 132 + col] = make_float2(acc[mi][ni][2], acc[mi][ni][3]);
        }
    }
    __syncthreads();

    if (head < 24) {
        const float* w = (head < 16) ? qw : kw;
        __half* base = (head < 16)
            ? g_qTh + (size_t)head * Ss * HD
            : g_kTh + (size_t)(head - 16) * Ss * HD;
        int nheads = (head < 16) ? NH : NKV;
#pragma unroll 1
        for (int it = 0; it < 16; it++) {
            int row = it * 8 + warp;
            int glob = r0 + row;
            int b = glob >> 11, s = glob & 2047;
            float x0 = S[row * 132 + lane];
            float x1 = S[row * 132 + lane + 32];
            float x2 = S[row * 132 + lane + 64];
            float x3 = S[row * 132 + lane + 96];
            float ssq = x0 * x0 + x1 * x1 + x2 * x2 + x3 * x3;
#pragma unroll
            for (int o = 16; o; o >>= 1) ssq += __shfl_xor_sync(0xffffffffu, ssq, o);
            float inv = rsqrtf(ssq * (1.0f / 128.0f) + 1e-6f);
            x0 = x0 * inv * w[lane];
            x1 = x1 * inv * w[lane + 32];
            x2 = x2 * inv * w[lane + 64];
            x3 = x3 * inv * w[lane + 96];
            const float* cp = cosb + (size_t)glob * HD;
            const float* sp = sinb + (size_t)glob * HD;
            float c0 = cp[lane], c1 = cp[lane + 32], c2 = cp[lane + 64], c3 = cp[lane + 96];
            float s0 = sp[lane], s1 = sp[lane + 32], s2 = sp[lane + 64], s3 = sp[lane + 96];
            __half* dst = base + ((size_t)b * nheads * Ss + s) * HD;
            dst[lane]      = __float2half_rn(x0 * c0 - x2 * s0);
            dst[lane + 32] = __float2half_rn(x1 * c1 - x3 * s1);
            dst[lane + 64] = __float2half_rn(x2 * c2 + x0 * s2);
            dst[lane + 96] = __float2half_rn(x3 * c3 + x1 * s3);
        }
    } else {
        int h = head - 24;
        int b = r0 >> 11, s0 = r0 & 2047;
        __half* dst = g_vTh + ((size_t)b * NKV + h) * Ss * HD;
#pragma unroll 1
        for (int it = 0; it < 16; it++) {
            int d = it * 8 + warp;
#pragma unroll
            for (int j = 0; j < 4; j++) {
                float v = S[(lane + 32 * j) * 132 + d];
                dst[(size_t)d * Ss + s0 + lane + 32 * j] = __float2half_rn(v);
            }
        }
    }
}

// ---------------------------------------------------------------------------
// O-projection GEMM
// ---------------------------------------------------------------------------
__global__ __launch_bounds__(256, 2) void gemm_f16(const __half* __restrict__ A,
                                                   const __half* __restrict__ B,
                                                   float* __restrict__ C,
                                                   int M, int N, int K) {
    extern __shared__ __half hsm[];
    __half* As = hsm;
    __half* Bs = hsm + 2 * TILE_H;

    const int tid  = threadIdx.x;
    const int warp = tid >> 5;
    const int lid  = tid & 31;
    const int wm = (warp >> 1) * 32;
    const int wn = (warp & 1) * 64;
    const int fr = lid >> 2;
    const int fc = lid & 3;

    const int r0 = blockIdx.y * 128;
    const int c0 = blockIdx.x * 128;

    float acc[2][8][4];
    gemm_mainloop(A, B, As, Bs, r0, c0, K, tid, wm, wn, acc);

#pragma unroll
    for (int mi = 0; mi < 2; mi++) {
        int row = r0 + wm + mi * 16 + fr;
        float* cp0 = C + (size_t)row * N + c0 + wn + fc * 2;
        float* cp1 = C + (size_t)(row + 8) * N + c0 + wn + fc * 2;
#pragma unroll
        for (int ni = 0; ni < 8; ni++) {
            *(float2*)(cp0 + ni * 8) = make_float2(acc[mi][ni][0], acc[mi][ni][1]);
            *(float2*)(cp1 + ni * 8) = make_float2(acc[mi][ni][2], acc[mi][ni][3]);
        }
    }
}

// ---------------------------------------------------------------------------
// fp16 tensorized flash attention, causal, GQA. ldmatrix fragment loads.
// ---------------------------------------------------------------------------
#define FQP 136
#define FVP 72
#define FSP 68
#define HOFF_KS   (64 * FQP)
#define HOFF_VT   (HOFF_KS + 2 * 64 * FQP)
#define HOFF_PS   (HOFF_VT + 2 * 128 * FVP)
#define FSM_TOTAL (98304 + 64*FSP*4 + 512)

__global__ __launch_bounds__(256, 1) void flash_mma_kernel() {
    extern __shared__ char fsm[];
    __half* Qs  = (__half*)fsm;
    __half* Ksb = Qs + HOFF_KS;
    __half* Vtb = Qs + HOFF_VT;
    __half* Ps  = Qs + HOFF_PS;
    float* Ssc  = (float*)(fsm + 98304);
    float* corr = Ssc + 64 * FSP;
    float* linv = corr + 64;

    const int tid  = threadIdx.x;
    const int warp = tid >> 5;
    const int lane = tid & 31;
    const int fr = lane >> 2;
    const int fc = lane & 3;
    const int l7  = lane & 7;
    const int l8  = (lane >> 3) & 1;
    const int l16 = lane >> 4;
    const int wmS = (warp >> 1) * 16;
    const int wnS = (warp & 1) * 32;
    const int wmO = wmS;
    const int wnO = (warp & 1) * 64;

    const int q0 = blockIdx.x * 64;
    const int h  = blockIdx.y;
    const int b  = blockIdx.z;
    const int hk = h >> 1;

    const __half* qb  = g_qTh + (((size_t)b * NH + h) * Ss + q0) * HD;
    const __half* kb  = g_kTh + ((size_t)b * NKV + hk) * Ss * HD;
    const __half* vtb = g_vTh + ((size_t)b * NKV + hk) * Ss * HD;

    // ldmatrix lane bases (bytes)
    const uint32_t qsu = s2u(Qs);
    const uint32_t ksu = s2u(Ksb);
    const uint32_t vsu = s2u(Vtb);
    const uint32_t psu = s2u(Ps);
    const uint32_t qoff = (uint32_t)(((wmS + l7 + l8 * 8) * FQP + l16 * 8) * 2);
    const uint32_t koff = (uint32_t)(((wnS + l7 + l16 * 8) * FQP + l8 * 8) * 2);
    const uint32_t poff = (uint32_t)(((wmO + l7 + l8 * 8) * FVP + l16 * 8) * 2);
    const uint32_t voff = (uint32_t)(((wnO + l7 + l16 * 8) * FVP + l8 * 8) * 2);

    const int srow = tid >> 2;
    const int ssub = tid & 3;
    float m_old = -1e30f, l_old = 0.f;

    float oa[8][4];
#pragma unroll
    for (int nf = 0; nf < 8; nf++)
#pragma unroll
        for (int j = 0; j < 4; j++) oa[nf][j] = 0.f;

    auto loadQ = [&]() {
#pragma unroll
        for (int i = 0; i < 4; i++) {
            int ch = tid + i * 256;
            int row = ch >> 4, kc = ch & 15;
            cpasync16(s2u(Qs + row * FQP + kc * 8), qb + (size_t)row * HD + kc * 8);
        }
    };
    auto loadK = [&](int j, int s) {
        __half* Kd = Ksb + s * 64 * FQP;
        const __half* src = kb + (size_t)(j * 64) * HD;
#pragma unroll
        for (int i = 0; i < 4; i++) {
            int ch = tid + i * 256;
            int row = ch >> 4, kc = ch & 15;
            cpasync16(s2u(Kd + row * FQP + kc * 8), src + (size_t)row * HD + kc * 8);
        }
    };
    auto loadV = [&](int j, int s) {
        __half* Vd = Vtb + s * 128 * FVP;
#pragma unroll
        for (int i = 0; i < 4; i++) {
            int ch = tid + i * 256;
            int row = ch >> 3, kc = ch & 7;
            cpasync16(s2u(Vd + row * FVP + kc * 8), vtb + (size_t)row * Ss + j * 64 + kc * 8);
        }
    };

    const int nt = blockIdx.x + 1;
    loadQ(); loadK(0, 0); loadV(0, 0);
    asm volatile("cp.async.commit_group;" ::: "memory");

    for (int j = 0; j < nt; j++) {
        int s = j & 1;
        if (j + 1 < nt) {
            loadK(j + 1, s ^ 1); loadV(j + 1, s ^ 1);
            asm volatile("cp.async.commit_group;" ::: "memory");
            asm volatile("cp.async.wait_group 1;" ::: "memory");
        } else {
            asm volatile("cp.async.wait_group 0;" ::: "memory");
        }
        __syncthreads();

        // ---- S = Q K^T ----
        const uint32_t kf = ksu + (uint32_t)(s * 64 * FQP * 2) + koff;
        float sa[4][4];
#pragma unroll
        for (int nf = 0; nf < 4; nf++)
#pragma unroll
            for (int t = 0; t < 4; t++) sa[nf][t] = 0.f;
#pragma unroll
        for (int kk = 0; kk < 8; kk++) {
            uint32_t a[4], bfr[4][2];
            ldmx4(a, qsu + qoff + kk * 32);
#pragma unroll
            for (int jj = 0; jj < 2; jj++) {
                uint32_t tmp[4];
                ldmx4(tmp, kf + jj * 16 * FQP * 2 + kk * 32);
                bfr[2 * jj][0]     = tmp[0];
                bfr[2 * jj][1]     = tmp[1];
                bfr[2 * jj + 1][0] = tmp[2];
                bfr[2 * jj + 1][1] = tmp[3];
            }
#pragma unroll
            for (int nf = 0; nf < 4; nf++) mma_f16(sa[nf], a, bfr[nf]);
        }
#pragma unroll
        for (int nf = 0; nf < 4; nf++) {
            int col = wnS + nf * 8 + 2 * fc;
            *(float2*)&Ssc[(wmS + fr) * FSP + col]     = make_float2(sa[nf][0], sa[nf][1]);
            *(float2*)&Ssc[(wmS + fr + 8) * FSP + col] = make_float2(sa[nf][2], sa[nf][3]);
        }
        __syncthreads();

        // ---- online softmax ----
        {
            float sv[16];
            float mx = -1e30f;
            int qglob = q0 + srow;
#pragma unroll
            for (int i = 0; i < 16; i++) {
                int c = ssub + 4 * i;
                float val = Ssc[srow * FSP + c] * SCALE;
                if (j * 64 + c > qglob) val = -1e9f;
                sv[i] = val;
                mx = fmaxf(mx, val);
            }
            mx = fmaxf(mx, __shfl_xor_sync(0xffffffffu, mx, 1));
            mx = fmaxf(mx, __shfl_xor_sync(0xffffffffu, mx, 2));
            float mnew = fmaxf(m_old, mx);
            float cr = __expf(m_old - mnew);
            float psum = 0.f;
#pragma unroll
            for (int i = 0; i < 16; i++) {
                float p = __expf(sv[i] - mnew);
                psum += p;
                Ps[srow * FVP + ssub + 4 * i] = __float2half_rn(p);
            }
            psum += __shfl_xor_sync(0xffffffffu, psum, 1);
            psum += __shfl_xor_sync(0xffffffffu, psum, 2);
            l_old = l_old * cr + psum;
            m_old = mnew;
            if (ssub == 0) corr[srow] = cr;
        }
        __syncthreads();

        // ---- O = O*corr + P V ----
        const uint32_t vf = vsu + (uint32_t)(s * 128 * FVP * 2) + voff;
        {
            float cr0 = corr[wmO + fr];
            float cr1 = corr[wmO + fr + 8];
#pragma unroll
            for (int nf = 0; nf < 8; nf++) {
                oa[nf][0] *= cr0; oa[nf][1] *= cr0;
                oa[nf][2] *= cr1; oa[nf][3] *= cr1;
            }
        }
#pragma unroll
        for (int kk = 0; kk < 4; kk++) {
            uint32_t a[4], bfr[8][2];
            ldmx4(a, psu + poff + kk * 32);
#pragma unroll
            for (int jj = 0; jj < 4; jj++) {
                uint32_t tmp[4];
                ldmx4(tmp, vf + jj * 16 * FVP * 2 + kk * 32);
                bfr[2 * jj][0]     = tmp[0];
                bfr[2 * jj][1]     = tmp[1];
                bfr[2 * jj + 1][0] = tmp[2];
                bfr[2 * jj + 1][1] = tmp[3];
            }
#pragma unroll
            for (int nf = 0; nf < 8; nf++) mma_f16(oa[nf], a, bfr[nf]);
        }
    }

    if (ssub == 0) linv[srow] = 1.0f / l_old;
    __syncthreads();

    float i0 = linv[wmO + fr];
    float i1 = linv[wmO + fr + 8];
    int row0 = q0 + wmO + fr;
    __half* d0 = g_attnH + ((size_t)(b * Ss + row0) * NH + h) * HD + wnO + 2 * fc;
    __half* d1 = g_attnH + ((size_t)(b * Ss + row0 + 8) * NH + h) * HD + wnO + 2 * fc;
#pragma unroll
    for (int nf = 0; nf < 8; nf++) {
        *(__half2*)(d0 + nf * 8) = __floats2half2_rn(oa[nf][0] * i0, oa[nf][1] * i0);
        *(__half2*)(d1 + nf * 8) = __floats2half2_rn(oa[nf][2] * i1, oa[nf][3] * i1);
    }
}

// ---------------------------------------------------------------------------
extern "C" void kernel_launch(void* const* d_in, const int* in_sizes, int n_in,
                              void* d_out, int out_size) {
    const float* x    = (const float*)d_in[0];
    const float* cosb = (const float*)d_in[1];
    const float* sinb = (const float*)d_in[2];
    const float* Wq = (const float*)d_in[4];
    const float* Wk = (const float*)d_in[5];
    const float* Wv = (const float*)d_in[6];
    const float* Wo = (const float*)d_in[7];
    const float* qw = (const float*)d_in[8];
    const float* kw = (const float*)d_in[9];
    float* out = (float*)d_out;

    __half *xH, *wqkvH, *woH, *attnH;
    cudaGetSymbolAddress((void**)&xH,    g_xH);
    cudaGetSymbolAddress((void**)&wqkvH, g_wqkvH);
    cudaGetSymbolAddress((void**)&woH,   g_woH);
    cudaGetSymbolAddress((void**)&attnH, g_attnH);

    cudaFuncSetAttribute(gemm_qkv_fused, cudaFuncAttributeMaxDynamicSharedMemorySize, GSM_TOTAL);
    cudaFuncSetAttribute(gemm_f16, cudaFuncAttributeMaxDynamicSharedMemorySize, GSM_TOTAL);
    cudaFuncSetAttribute(flash_mma_kernel, cudaFuncAttributeMaxDynamicSharedMemorySize, FSM_TOTAL);

    // fp16 packs
    cvt_f2h_kernel<<<(MROWS * HID) / 2048, 256>>>(x, xH, MROWS * HID);
    cvt_qkv_kernel<<<(NQKV * HID) / 2048, 256>>>(Wq, Wk, Wv, wqkvH);
    cvt_f2h_kernel<<<(HID * QDIM) / 2048, 256>>>(Wo, woH, HID * QDIM);

    // Fused QKV projection + RMSNorm + RoPE + transpose
    gemm_qkv_fused<<<dim3(NQKV / 128, MROWS / 128), 256, GSM_TOTAL>>>(
        xH, wqkvH, cosb, sinb, qw, kw);

    // fp16 tensorized causal flash attention
    flash_mma_kernel<<<dim3(Ss / 64, NH, Bb), 256, FSM_TOTAL>>>();

    // Output projection
    gemm_f16<<<dim3(HID / 128, MROWS / 128), 256, GSM_TOTAL>>>(attnH, woH, out, MROWS, HID, QDIM);
}